// round 12
// baseline (speedup 1.0000x reference)
#include <cuda_runtime.h>
#include <math.h>

// Problem constants: T=768, B=4, E=256, H=8, HD=32, 32 "bh" heads.
// Q scale folded with log2(e): scores arrive in log2 domain, exp(s) == 2^s'.
#define QSCALE 0.25500917392938054f   // (1/sqrt(32)) * log2(e)

// ---------------- scratch (static device globals; no allocation) ----------------
__device__ float g_q[786432];        // [bh=32][t=768][hd=32]
__device__ float g_k[786432];
__device__ float g_v[786432];
__device__ float g_obuf[5505024];    // [branch=7][bh=32][t=768][hd=32]
__device__ float g_G[458752];        // [7][y=256][x=256]
__device__ float g_tmpT[458752];     // [7][a=256][y=256]
__device__ float g_MTcat[458752];    // [n=256][k=1792]
__device__ float g_c1[256];
__device__ float g_biasv[256];

// Segments partition the columns: L=[0,300) A=[300,550) V=[550,768)
__constant__ int c_segS[3] = {0, 300, 550};
__constant__ int c_segE[3] = {300, 550, 768};
// branch -> segment bitmask: lav, la, lv, av, l, a, v
__constant__ int c_bmask[7] = {7, 3, 5, 6, 1, 2, 4};

// FMA-pipe 2^x (no MUFU). |x| < ~80, rel err ~1e-7 (deg-6 Taylor on [-0.5,0.5]).
__device__ __forceinline__ float fexp2(float x)
{
    float z = x + 12582912.0f;            // 1.5*2^23: round-to-nearest-int trick
    int   n = __float_as_int(z);          // low bits hold round(x)
    float f = x - (z - 12582912.0f);      // frac in [-0.5, 0.5], exact
    float p = 1.5402387e-4f;
    p = fmaf(p, f, 1.3333558e-3f);
    p = fmaf(p, f, 9.6181291e-3f);
    p = fmaf(p, f, 5.5504109e-2f);
    p = fmaf(p, f, 2.4022651e-1f);
    p = fmaf(p, f, 6.9314718e-1f);
    p = fmaf(p, f, 1.0f);
    return __int_as_float(__float_as_int(p) + (n << 23));
}

// ---------------- small tiled SGEMM (32x32 tiles, K-step 32), coalesced ----------------
__global__ void __launch_bounds__(256) gemm_small(
    const float* __restrict__ A, int a_sm, int a_sk, int a_bz,
    const float* __restrict__ B, int b_sn, int b_sk, int b_bz,
    float* __restrict__ C, int c_sm, int c_bz,
    int K)
{
    A += (size_t)blockIdx.z * a_bz;
    B += (size_t)blockIdx.z * b_bz;
    C += (size_t)blockIdx.z * c_bz;
    int m0 = blockIdx.y * 32, n0 = blockIdx.x * 32;
    __shared__ float As[32][36], Bs[32][36];
    int tid = threadIdx.x;
    int tx = tid & 15, ty = tid >> 4;
    float acc[2][2] = {};
    for (int k0 = 0; k0 < K; k0 += 32) {
        if (a_sk == 1) {   // k contiguous: kk fastest across tid
            #pragma unroll
            for (int i = 0; i < 4; i++) {
                int idx = tid + i * 256;
                int mm = idx >> 5, kk = idx & 31;
                As[kk][mm] = A[(size_t)(m0 + mm) * a_sm + (k0 + kk)];
            }
        } else {           // m contiguous: mm fastest across tid
            #pragma unroll
            for (int i = 0; i < 4; i++) {
                int idx = tid + i * 256;
                int mm = idx & 31, kk = idx >> 5;
                As[kk][mm] = A[(size_t)(m0 + mm) + (size_t)(k0 + kk) * a_sk];
            }
        }
        if (b_sk == 1) {
            #pragma unroll
            for (int i = 0; i < 4; i++) {
                int idx = tid + i * 256;
                int mm = idx >> 5, kk = idx & 31;
                Bs[kk][mm] = B[(size_t)(n0 + mm) * b_sn + (k0 + kk)];
            }
        } else {
            #pragma unroll
            for (int i = 0; i < 4; i++) {
                int idx = tid + i * 256;
                int mm = idx & 31, kk = idx >> 5;
                Bs[kk][mm] = B[(size_t)(n0 + mm) + (size_t)(k0 + kk) * b_sk];
            }
        }
        __syncthreads();
        #pragma unroll
        for (int kk = 0; kk < 32; kk++) {
            float2 a = *(const float2*)&As[kk][ty * 2];
            float2 b = *(const float2*)&Bs[kk][tx * 2];
            acc[0][0] = fmaf(a.x, b.x, acc[0][0]);
            acc[0][1] = fmaf(a.x, b.y, acc[0][1]);
            acc[1][0] = fmaf(a.y, b.x, acc[1][0]);
            acc[1][1] = fmaf(a.y, b.y, acc[1][1]);
        }
        __syncthreads();
    }
    #pragma unroll
    for (int i = 0; i < 2; i++)
        #pragma unroll
        for (int j = 0; j < 2; j++)
            C[(size_t)(m0 + ty * 2 + i) * c_sm + (n0 + tx * 2 + j)] = acc[i][j];
}

// ---------------- QKV projection, scattered to head-major ----------------
__global__ void __launch_bounds__(256) proj_kernel(
    const float* __restrict__ q_in, const float* __restrict__ k_in,
    const float* __restrict__ v_in, const float* __restrict__ W,
    const float* __restrict__ bias)
{
    int z = blockIdx.z;
    const float* A = (z == 0) ? q_in : (z == 1) ? k_in : v_in;
    float* dst = (z == 0) ? g_q : (z == 1) ? g_k : g_v;
    const float* Bw = W + (size_t)z * 65536;
    const float* bz = bias + z * 256;
    float scale = (z == 0) ? QSCALE : 1.0f;

    int m0 = blockIdx.y * 64, n0 = blockIdx.x * 64;
    __shared__ float As[16][68], Bs[16][68];
    int tid = threadIdx.x;
    int tx = tid & 15, ty = tid >> 4;
    float acc[4][4] = {};
    for (int k0 = 0; k0 < 256; k0 += 16) {
        #pragma unroll
        for (int i = 0; i < 4; i++) {
            int idx = tid + i * 256;
            int mm = idx >> 4, kk = idx & 15;
            As[kk][mm] = A[(size_t)(m0 + mm) * 256 + (k0 + kk)];
            Bs[kk][mm] = Bw[(size_t)(n0 + mm) * 256 + (k0 + kk)];
        }
        __syncthreads();
        #pragma unroll
        for (int kk = 0; kk < 16; kk++) {
            float4 a = *(const float4*)&As[kk][ty * 4];
            float4 b = *(const float4*)&Bs[kk][tx * 4];
            acc[0][0] = fmaf(a.x, b.x, acc[0][0]);
            acc[0][1] = fmaf(a.x, b.y, acc[0][1]);
            acc[0][2] = fmaf(a.x, b.z, acc[0][2]);
            acc[0][3] = fmaf(a.x, b.w, acc[0][3]);
            acc[1][0] = fmaf(a.y, b.x, acc[1][0]);
            acc[1][1] = fmaf(a.y, b.y, acc[1][1]);
            acc[1][2] = fmaf(a.y, b.z, acc[1][2]);
            acc[1][3] = fmaf(a.y, b.w, acc[1][3]);
            acc[2][0] = fmaf(a.z, b.x, acc[2][0]);
            acc[2][1] = fmaf(a.z, b.y, acc[2][1]);
            acc[2][2] = fmaf(a.z, b.z, acc[2][2]);
            acc[2][3] = fmaf(a.z, b.w, acc[2][3]);
            acc[3][0] = fmaf(a.w, b.x, acc[3][0]);
            acc[3][1] = fmaf(a.w, b.y, acc[3][1]);
            acc[3][2] = fmaf(a.w, b.z, acc[3][2]);
            acc[3][3] = fmaf(a.w, b.w, acc[3][3]);
        }
        __syncthreads();
    }
    #pragma unroll
    for (int i = 0; i < 4; i++) {
        int m = m0 + ty * 4 + i;
        int t = m >> 2, b = m & 3;
        #pragma unroll
        for (int j = 0; j < 4; j++) {
            int n = n0 + tx * 4 + j;
            int h = n >> 5, hd = n & 31;
            float val = (acc[i][j] + bz[n]) * scale;
            dst[(size_t)((b * 8 + h) * 768 + t) * 32 + hd] = val;
        }
    }
}

// ---------------- fully fused flash attention + branch combine ----------------
// Best-known config: 64-row tiles, single-buffered K/V, 4x4 S register tile,
// FMA-pipe exp2, float4 PV loads.
__global__ void __launch_bounds__(256) flash_kernel()
{
    const int segS[3] = {0, 300, 550};
    const int segE[3] = {300, 550, 768};
    const int bmask[7] = {7, 3, 5, 6, 1, 2, 4};

    int bh = blockIdx.y, t0 = blockIdx.x * 64;
    int tid = threadIdx.x;
    int tx = tid & 15, ty = tid >> 4;   // S mapping: rows ty*4+i, cols tx*4+j
    int h2 = tx * 2;                    // PV mapping: rows ty+16k, hd pair h2

    __shared__ float QsT[32][68], KsT[32][68];
    __shared__ float Ws[64][68];
    __shared__ float Vs[32][68];        // stride 68 floats -> 16B-aligned rows
    __shared__ float sl_s[3][64];
    __shared__ float srd[7][64];

    const float* qbase = g_q + (size_t)bh * 24576 + (size_t)t0 * 32;
    const float* kb = g_k + (size_t)bh * 24576;
    const float* vb = g_v + (size_t)bh * 24576;

    #pragma unroll
    for (int i = 0; i < 8; i++) {
        int idx = tid + i * 256;
        int r = idx >> 5, kk = idx & 31;
        QsT[kk][r] = qbase[r * 32 + kk];
    }

    float acc[3][4][2] = {};

    #pragma unroll
    for (int seg = 0; seg < 3; seg++) {
        int ss = segS[seg], se = segE[seg];
        int ts = ss >> 6, te = (se + 63) >> 6;
        float lpart[4];
        #pragma unroll
        for (int i = 0; i < 4; i++) lpart[i] = 0.0f;

        for (int st = ts; st < te; st++) {
            int s0 = st * 64;
            __syncthreads();
            #pragma unroll
            for (int i = 0; i < 8; i++) {
                int idx = tid + i * 256;
                int r = idx >> 5, kk = idx & 31;
                KsT[kk][r] = kb[(size_t)(s0 + r) * 32 + kk];
            }
            #pragma unroll
            for (int i = 0; i < 8; i++) {
                int idx = tid + i * 256;
                int sc = idx >> 5, hd = idx & 31;
                Vs[hd][sc] = vb[(size_t)(s0 + sc) * 32 + hd];
            }
            __syncthreads();

            // S tile 4x4: rows ty*4+i, cols tx*4+j
            float sv[4][4] = {};
            #pragma unroll
            for (int kk = 0; kk < 32; kk++) {
                float4 a = *(const float4*)&QsT[kk][ty * 4];
                float4 b = *(const float4*)&KsT[kk][tx * 4];
                sv[0][0] = fmaf(a.x, b.x, sv[0][0]);
                sv[0][1] = fmaf(a.x, b.y, sv[0][1]);
                sv[0][2] = fmaf(a.x, b.z, sv[0][2]);
                sv[0][3] = fmaf(a.x, b.w, sv[0][3]);
                sv[1][0] = fmaf(a.y, b.x, sv[1][0]);
                sv[1][1] = fmaf(a.y, b.y, sv[1][1]);
                sv[1][2] = fmaf(a.y, b.z, sv[1][2]);
                sv[1][3] = fmaf(a.y, b.w, sv[1][3]);
                sv[2][0] = fmaf(a.z, b.x, sv[2][0]);
                sv[2][1] = fmaf(a.z, b.y, sv[2][1]);
                sv[2][2] = fmaf(a.z, b.z, sv[2][2]);
                sv[2][3] = fmaf(a.z, b.w, sv[2][3]);
                sv[3][0] = fmaf(a.w, b.x, sv[3][0]);
                sv[3][1] = fmaf(a.w, b.y, sv[3][1]);
                sv[3][2] = fmaf(a.w, b.z, sv[3][2]);
                sv[3][3] = fmaf(a.w, b.w, sv[3][3]);
            }

            // exp (bounded -> no max subtraction), per-row partial sums, W store
            int cb = s0 + tx * 4;
            #pragma unroll
            for (int i = 0; i < 4; i++) {
                float4 w;
                w.x = (cb + 0 >= ss && cb + 0 < se) ? fexp2(sv[i][0]) : 0.0f;
                w.y = (cb + 1 >= ss && cb + 1 < se) ? fexp2(sv[i][1]) : 0.0f;
                w.z = (cb + 2 >= ss && cb + 2 < se) ? fexp2(sv[i][2]) : 0.0f;
                w.w = (cb + 3 >= ss && cb + 3 < se) ? fexp2(sv[i][3]) : 0.0f;
                lpart[i] += (w.x + w.y) + (w.z + w.w);
                *(float4*)&Ws[ty * 4 + i][tx * 4] = w;
            }
            __syncthreads();

            // O accumulate: acc[seg] += Ws @ Vs  (float4 loads)
            #pragma unroll 4
            for (int s = 0; s < 64; s += 4) {
                float4 va = *(const float4*)&Vs[h2][s];
                float4 vbp = *(const float4*)&Vs[h2 + 1][s];
                #pragma unroll
                for (int k = 0; k < 4; k++) {
                    float4 w = *(const float4*)&Ws[ty + 16 * k][s];
                    acc[seg][k][0] = fmaf(w.w, va.w, fmaf(w.z, va.z,
                                     fmaf(w.y, va.y, fmaf(w.x, va.x, acc[seg][k][0]))));
                    acc[seg][k][1] = fmaf(w.w, vbp.w, fmaf(w.z, vbp.z,
                                     fmaf(w.y, vbp.y, fmaf(w.x, vbp.x, acc[seg][k][1]))));
                }
            }
        }
        // reduce per-row l across the 16 column-threads (width-16 shuffle)
        #pragma unroll
        for (int i = 0; i < 4; i++) {
            float lf = lpart[i];
            #pragma unroll
            for (int o = 8; o; o >>= 1)
                lf += __shfl_xor_sync(0xffffffffu, lf, o, 16);
            if (tx == 0) sl_s[seg][ty * 4 + i] = lf;
        }
    }
    __syncthreads();

    // per-row reciprocal denominators for all 7 branches (once)
    if (tid < 64) {
        float lr[3] = {sl_s[0][tid], sl_s[1][tid], sl_s[2][tid]};
        #pragma unroll
        for (int br = 0; br < 7; br++) {
            int mask = bmask[br];
            float den = 0.0f;
            #pragma unroll
            for (int s = 0; s < 3; s++)
                if ((mask >> s) & 1) den += lr[s];
            srd[br][tid] = __frcp_rn(den);
        }
    }
    __syncthreads();

    // combine: 7 branch outputs straight from registers
    #pragma unroll
    for (int k = 0; k < 4; k++) {
        int r = ty + 16 * k;
        int t = t0 + r;
        int seg_t = (t < 300) ? 0 : (t < 550) ? 1 : 2;
        #pragma unroll
        for (int br = 0; br < 7; br++) {
            int mask = bmask[br];
            float2 val = make_float2(0.0f, 0.0f);
            if ((mask >> seg_t) & 1) {
                float num0 = 0.0f, num1 = 0.0f;
                #pragma unroll
                for (int s = 0; s < 3; s++) {
                    if ((mask >> s) & 1) {
                        num0 += acc[s][k][0];
                        num1 += acc[s][k][1];
                    }
                }
                float rd = srd[br][r];
                val.x = num0 * rd;
                val.y = num1 * rd;
            }
            *(float2*)&g_obuf[(size_t)br * 786432 + (size_t)bh * 24576 +
                              (size_t)t * 32 + h2] = val;
        }
    }
}

// ---------------- build G_i = sums of s_*_w column blocks ----------------
__global__ void __launch_bounds__(256) gmat_kernel(
    const float* __restrict__ sl, const float* __restrict__ sa,
    const float* __restrict__ sv)
{
    int idx = blockIdx.x * 256 + threadIdx.x;
    int i = idx >> 16;
    int y = (idx >> 8) & 255;
    int x = idx & 255;
    size_t r = (size_t)y * 1024;
    float v = 0.0f;
    switch (i) {
        case 0: v = sl[r + x]       + sa[r + x]       + sv[r + x];   break;
        case 1: v = sl[r + 256 + x] + sa[r + 256 + x];               break;
        case 2: v = sl[r + 512 + x] + sv[r + 256 + x];               break;
        case 3: v = sa[r + 512 + x] + sv[r + 512 + x];               break;
        case 4: v = sl[r + 768 + x];                                 break;
        case 5: v = sa[r + 768 + x];                                 break;
        case 6: v = sv[r + 768 + x];                                 break;
    }
    g_G[idx] = v;
}

// ---------------- bias fold, stage 1 ----------------
__global__ void __launch_bounds__(256) bias1_kernel(
    const float* __restrict__ out_b, const float* __restrict__ slb,
    const float* __restrict__ sab, const float* __restrict__ svb)
{
    int y = blockIdx.x;
    int tid = threadIdx.x;
    __shared__ float red[256];
    float p = 0.0f;
    #pragma unroll
    for (int i = 0; i < 7; i++)
        p += out_b[i * 256 + tid] * g_G[i * 65536 + y * 256 + tid];
    red[tid] = p;
    __syncthreads();
    for (int o = 128; o; o >>= 1) {
        if (tid < o) red[tid] += red[tid + o];
        __syncthreads();
    }
    if (tid == 0) g_c1[y] = red[0] + slb[y] + sab[y] + svb[y];
}

// ---------------- bias fold, stage 2 ----------------
__global__ void __launch_bounds__(256) bias2_kernel(
    const float* __restrict__ fb, const float* __restrict__ fw)
{
    int n = blockIdx.x;
    int tid = threadIdx.x;
    __shared__ float red[256];
    red[tid] = g_c1[tid] * fw[(size_t)n * 256 + tid];
    __syncthreads();
    for (int o = 128; o; o >>= 1) {
        if (tid < o) red[tid] += red[tid + o];
        __syncthreads();
    }
    if (tid == 0) g_biasv[n] = red[0] + fb[n];
}

// ---------------- final fused GEMM: out = sum_i o_i @ M_i + bias (dead-branch skip) ----------------
__global__ void __launch_bounds__(256) final_kernel(float* __restrict__ out)
{
    int m0 = blockIdx.y * 64, n0 = blockIdx.x * 32;
    __shared__ float As[32][68], Bs[32][36];
    int tid = threadIdx.x;
    int tx = tid & 15, ty = tid >> 4;

    int tb0 = m0 >> 2, tb1 = (m0 + 63) >> 2;
    int bm = 0;
    #pragma unroll
    for (int br = 0; br < 7; br++) {
        int mk = c_bmask[br];
        #pragma unroll
        for (int s = 0; s < 3; s++)
            if (((mk >> s) & 1) && tb0 < c_segE[s] && tb1 >= c_segS[s]) bm |= 1 << br;
    }

    float acc[4][2] = {};
    for (int k0 = 0; k0 < 1792; k0 += 32) {
        int ibr = k0 >> 8;
        if (!((bm >> ibr) & 1)) continue;
        int h = (k0 & 255) >> 5;
        const float* Abase = g_obuf + (size_t)ibr * 786432 + (size_t)h * 24576;
        #pragma unroll
        for (int i = 0; i < 8; i++) {
            int idx = tid + i * 256;
            int mm = idx >> 5, kk = idx & 31;
            int m = m0 + mm;
            int t = m >> 2, b = m & 3;
            As[kk][mm] = Abase[(size_t)b * 196608 + (size_t)t * 32 + kk];
        }
        #pragma unroll
        for (int i = 0; i < 4; i++) {
            int idx = tid + i * 256;
            int nn = idx >> 5, kk = idx & 31;
            Bs[kk][nn] = g_MTcat[(size_t)(n0 + nn) * 1792 + k0 + kk];
        }
        __syncthreads();
        #pragma unroll
        for (int kk = 0; kk < 32; kk++) {
            float4 a = *(const float4*)&As[kk][ty * 4];
            float2 b = *(const float2*)&Bs[kk][tx * 2];
            acc[0][0] = fmaf(a.x, b.x, acc[0][0]);
            acc[0][1] = fmaf(a.x, b.y, acc[0][1]);
            acc[1][0] = fmaf(a.y, b.x, acc[1][0]);
            acc[1][1] = fmaf(a.y, b.y, acc[1][1]);
            acc[2][0] = fmaf(a.z, b.x, acc[2][0]);
            acc[2][1] = fmaf(a.z, b.y, acc[2][1]);
            acc[3][0] = fmaf(a.w, b.x, acc[3][0]);
            acc[3][1] = fmaf(a.w, b.y, acc[3][1]);
        }
        __syncthreads();
    }
    #pragma unroll
    for (int i = 0; i < 4; i++) {
        int m = m0 + ty * 4 + i;
        #pragma unroll
        for (int j = 0; j < 2; j++) {
            int n = n0 + tx * 2 + j;
            out[(size_t)m * 256 + n] = acc[i][j] + g_biasv[n];
        }
    }
}

// ---------------- launch (serial; ordered so flash is the 4th launch for ncu) ----------------
extern "C" void kernel_launch(void* const* d_in, const int* in_sizes, int n_in,
                              void* d_out, int out_size)
{
    const float* query     = (const float*)d_in[0];
    const float* key       = (const float*)d_in[1];
    const float* value     = (const float*)d_in[2];
    const float* in_proj_w = (const float*)d_in[3];
    const float* in_proj_b = (const float*)d_in[4];
    const float* out_w     = (const float*)d_in[5];
    const float* out_b     = (const float*)d_in[6];
    const float* s_l_w     = (const float*)d_in[7];
    const float* s_l_b     = (const float*)d_in[8];
    const float* s_a_w     = (const float*)d_in[9];
    const float* s_a_b     = (const float*)d_in[10];
    const float* s_v_w     = (const float*)d_in[11];
    const float* s_v_b     = (const float*)d_in[12];
    const float* final_w   = (const float*)d_in[13];
    const float* final_b   = (const float*)d_in[14];
    float* out = (float*)d_out;
    (void)in_sizes; (void)n_in; (void)out_size;

    float *p_G, *p_tmpT, *p_MTcat;
    cudaGetSymbolAddress((void**)&p_G,      g_G);
    cudaGetSymbolAddress((void**)&p_tmpT,   g_tmpT);
    cudaGetSymbolAddress((void**)&p_MTcat,  g_MTcat);

    // launch #1: q/k/v projections -> head-major
    proj_kernel<<<dim3(4, 48, 3), 256>>>(query, key, value, in_proj_w, in_proj_b);

    // launch #2: G_i (weights only; independent of proj/flash)
    gmat_kernel<<<1792, 256>>>(s_l_w, s_a_w, s_v_w);

    // launch #3: tmpT[i][a][y] = sum_x out_w[i][x][a] * G_i[y][x]
    gemm_small<<<dim3(8, 8, 7), 256>>>(
        out_w, 1, 256, 65536,
        p_G, 256, 1, 65536,
        p_tmpT, 256, 65536, 256);

    // launch #4: fused flash attention + branch combine  (ncu profiles this one)
    flash_kernel<<<dim3(12, 32), 256>>>();

    // launch #5: MTcat[n][i*256+a] = sum_y final_w[n][y] * tmpT[i][a][y]
    gemm_small<<<dim3(8, 8, 7), 256>>>(
        final_w, 256, 1, 0,
        p_tmpT, 256, 1, 65536,
        p_MTcat, 1792, 256, 256);

    // launches #6,#7: fold biases
    bias1_kernel<<<256, 256>>>(out_b, s_l_b, s_a_b, s_v_b);
    bias2_kernel<<<256, 256>>>(final_b, final_w);

    // launch #8: out = sum_i o_i @ M_i + bias
    final_kernel<<<dim3(8, 48), 256>>>(out);
}

// round 13
// speedup vs baseline: 1.2004x; 1.2004x over previous
#include <cuda_runtime.h>
#include <math.h>

// Problem constants: T=768, B=4, E=256, H=8, HD=32, 32 "bh" heads.
// Q scale folded with log2(e): scores arrive in log2 domain, exp(s) == 2^s'.
#define QSCALE 0.25500917392938054f   // (1/sqrt(32)) * log2(e)

// ---------------- scratch (static device globals; no allocation) ----------------
__device__ float g_q[786432];        // [bh=32][t=768][hd=32]
__device__ float g_k[786432];
__device__ float g_v[786432];
__device__ float g_obuf[5505024];    // [branch=7][bh=32][t=768][hd=32]
__device__ float g_G[458752];        // [7][y=256][x=256]
__device__ float g_tmpT[458752];     // [7][a=256][y=256]
__device__ float g_MTcat[458752];    // [n=256][k=1792]
__device__ float g_c1[256];
__device__ float g_biasv[256];

// Segments partition the columns: L=[0,300) A=[300,550) V=[550,768)
__constant__ int c_segS[3] = {0, 300, 550};
__constant__ int c_segE[3] = {300, 550, 768};
// branch -> segment bitmask: lav, la, lv, av, l, a, v
__constant__ int c_bmask[7] = {7, 3, 5, 6, 1, 2, 4};

// FMA-pipe 2^x (no MUFU). |x| < ~80, rel err ~1e-7 (deg-6 Taylor on [-0.5,0.5]).
__device__ __forceinline__ float fexp2(float x)
{
    float z = x + 12582912.0f;            // 1.5*2^23: round-to-nearest-int trick
    int   n = __float_as_int(z);          // low bits hold round(x)
    float f = x - (z - 12582912.0f);      // frac in [-0.5, 0.5], exact
    float p = 1.5402387e-4f;
    p = fmaf(p, f, 1.3333558e-3f);
    p = fmaf(p, f, 9.6181291e-3f);
    p = fmaf(p, f, 5.5504109e-2f);
    p = fmaf(p, f, 2.4022651e-1f);
    p = fmaf(p, f, 6.9314718e-1f);
    p = fmaf(p, f, 1.0f);
    return __int_as_float(__float_as_int(p) + (n << 23));
}

// ---------------- small tiled SGEMM (32x32 tiles, K-step 32), coalesced ----------------
__global__ void __launch_bounds__(256) gemm_small(
    const float* __restrict__ A, int a_sm, int a_sk, int a_bz,
    const float* __restrict__ B, int b_sn, int b_sk, int b_bz,
    float* __restrict__ C, int c_sm, int c_bz,
    int K)
{
    A += (size_t)blockIdx.z * a_bz;
    B += (size_t)blockIdx.z * b_bz;
    C += (size_t)blockIdx.z * c_bz;
    int m0 = blockIdx.y * 32, n0 = blockIdx.x * 32;
    __shared__ float As[32][36], Bs[32][36];
    int tid = threadIdx.x;
    int tx = tid & 15, ty = tid >> 4;
    float acc[2][2] = {};
    for (int k0 = 0; k0 < K; k0 += 32) {
        if (a_sk == 1) {   // k contiguous: kk fastest across tid
            #pragma unroll
            for (int i = 0; i < 4; i++) {
                int idx = tid + i * 256;
                int mm = idx >> 5, kk = idx & 31;
                As[kk][mm] = A[(size_t)(m0 + mm) * a_sm + (k0 + kk)];
            }
        } else {           // m contiguous: mm fastest across tid
            #pragma unroll
            for (int i = 0; i < 4; i++) {
                int idx = tid + i * 256;
                int mm = idx & 31, kk = idx >> 5;
                As[kk][mm] = A[(size_t)(m0 + mm) + (size_t)(k0 + kk) * a_sk];
            }
        }
        if (b_sk == 1) {
            #pragma unroll
            for (int i = 0; i < 4; i++) {
                int idx = tid + i * 256;
                int mm = idx >> 5, kk = idx & 31;
                Bs[kk][mm] = B[(size_t)(n0 + mm) * b_sn + (k0 + kk)];
            }
        } else {
            #pragma unroll
            for (int i = 0; i < 4; i++) {
                int idx = tid + i * 256;
                int mm = idx & 31, kk = idx >> 5;
                Bs[kk][mm] = B[(size_t)(n0 + mm) + (size_t)(k0 + kk) * b_sk];
            }
        }
        __syncthreads();
        #pragma unroll
        for (int kk = 0; kk < 32; kk++) {
            float2 a = *(const float2*)&As[kk][ty * 2];
            float2 b = *(const float2*)&Bs[kk][tx * 2];
            acc[0][0] = fmaf(a.x, b.x, acc[0][0]);
            acc[0][1] = fmaf(a.x, b.y, acc[0][1]);
            acc[1][0] = fmaf(a.y, b.x, acc[1][0]);
            acc[1][1] = fmaf(a.y, b.y, acc[1][1]);
        }
        __syncthreads();
    }
    #pragma unroll
    for (int i = 0; i < 2; i++)
        #pragma unroll
        for (int j = 0; j < 2; j++)
            C[(size_t)(m0 + ty * 2 + i) * c_sm + (n0 + tx * 2 + j)] = acc[i][j];
}

// ---------------- QKV projection, scattered to head-major ----------------
__global__ void __launch_bounds__(256) proj_kernel(
    const float* __restrict__ q_in, const float* __restrict__ k_in,
    const float* __restrict__ v_in, const float* __restrict__ W,
    const float* __restrict__ bias)
{
    int z = blockIdx.z;
    const float* A = (z == 0) ? q_in : (z == 1) ? k_in : v_in;
    float* dst = (z == 0) ? g_q : (z == 1) ? g_k : g_v;
    const float* Bw = W + (size_t)z * 65536;
    const float* bz = bias + z * 256;
    float scale = (z == 0) ? QSCALE : 1.0f;

    int m0 = blockIdx.y * 64, n0 = blockIdx.x * 64;
    __shared__ float As[16][68], Bs[16][68];
    int tid = threadIdx.x;
    int tx = tid & 15, ty = tid >> 4;
    float acc[4][4] = {};
    for (int k0 = 0; k0 < 256; k0 += 16) {
        #pragma unroll
        for (int i = 0; i < 4; i++) {
            int idx = tid + i * 256;
            int mm = idx >> 4, kk = idx & 15;
            As[kk][mm] = A[(size_t)(m0 + mm) * 256 + (k0 + kk)];
            Bs[kk][mm] = Bw[(size_t)(n0 + mm) * 256 + (k0 + kk)];
        }
        __syncthreads();
        #pragma unroll
        for (int kk = 0; kk < 16; kk++) {
            float4 a = *(const float4*)&As[kk][ty * 4];
            float4 b = *(const float4*)&Bs[kk][tx * 4];
            acc[0][0] = fmaf(a.x, b.x, acc[0][0]);
            acc[0][1] = fmaf(a.x, b.y, acc[0][1]);
            acc[0][2] = fmaf(a.x, b.z, acc[0][2]);
            acc[0][3] = fmaf(a.x, b.w, acc[0][3]);
            acc[1][0] = fmaf(a.y, b.x, acc[1][0]);
            acc[1][1] = fmaf(a.y, b.y, acc[1][1]);
            acc[1][2] = fmaf(a.y, b.z, acc[1][2]);
            acc[1][3] = fmaf(a.y, b.w, acc[1][3]);
            acc[2][0] = fmaf(a.z, b.x, acc[2][0]);
            acc[2][1] = fmaf(a.z, b.y, acc[2][1]);
            acc[2][2] = fmaf(a.z, b.z, acc[2][2]);
            acc[2][3] = fmaf(a.z, b.w, acc[2][3]);
            acc[3][0] = fmaf(a.w, b.x, acc[3][0]);
            acc[3][1] = fmaf(a.w, b.y, acc[3][1]);
            acc[3][2] = fmaf(a.w, b.z, acc[3][2]);
            acc[3][3] = fmaf(a.w, b.w, acc[3][3]);
        }
        __syncthreads();
    }
    #pragma unroll
    for (int i = 0; i < 4; i++) {
        int m = m0 + ty * 4 + i;
        int t = m >> 2, b = m & 3;
        #pragma unroll
        for (int j = 0; j < 4; j++) {
            int n = n0 + tx * 4 + j;
            int h = n >> 5, hd = n & 31;
            float val = (acc[i][j] + bz[n]) * scale;
            dst[(size_t)((b * 8 + h) * 768 + t) * 32 + hd] = val;
        }
    }
}

// ---------------- fully fused flash attention + branch combine ----------------
// R6-proven body (float2 PV, Vs stride 66) + launch_bounds(256,3) to force
// regs<=80 -> 3 CTAs/SM (profile showed occ=22%, register-limited at 92 regs).
__global__ void __launch_bounds__(256, 3) flash_kernel()
{
    const int segS[3] = {0, 300, 550};
    const int segE[3] = {300, 550, 768};
    const int bmask[7] = {7, 3, 5, 6, 1, 2, 4};

    int bh = blockIdx.y, t0 = blockIdx.x * 64;
    int tid = threadIdx.x;
    int tx = tid & 15, ty = tid >> 4;   // S mapping: rows ty*4+i, cols tx*4+j
    int h2 = tx * 2;                    // PV mapping: rows ty+16k, hd pair h2

    __shared__ float QsT[32][68], KsT[32][68];
    __shared__ float Ws[64][68];
    __shared__ float Vs[32][66];
    __shared__ float sl_s[3][64];
    __shared__ float srd[7][64];

    const float* qbase = g_q + (size_t)bh * 24576 + (size_t)t0 * 32;
    const float* kb = g_k + (size_t)bh * 24576;
    const float* vb = g_v + (size_t)bh * 24576;

    #pragma unroll
    for (int i = 0; i < 8; i++) {
        int idx = tid + i * 256;
        int r = idx >> 5, kk = idx & 31;
        QsT[kk][r] = qbase[r * 32 + kk];
    }

    float acc[3][4][2] = {};

    #pragma unroll
    for (int seg = 0; seg < 3; seg++) {
        int ss = segS[seg], se = segE[seg];
        int ts = ss >> 6, te = (se + 63) >> 6;
        float lpart[4];
        #pragma unroll
        for (int i = 0; i < 4; i++) lpart[i] = 0.0f;

        for (int st = ts; st < te; st++) {
            int s0 = st * 64;
            __syncthreads();
            #pragma unroll
            for (int i = 0; i < 8; i++) {
                int idx = tid + i * 256;
                int r = idx >> 5, kk = idx & 31;
                KsT[kk][r] = kb[(size_t)(s0 + r) * 32 + kk];
            }
            #pragma unroll
            for (int i = 0; i < 8; i++) {
                int idx = tid + i * 256;
                int sc = idx >> 5, hd = idx & 31;
                Vs[hd][sc] = vb[(size_t)(s0 + sc) * 32 + hd];
            }
            __syncthreads();

            // S tile 4x4: rows ty*4+i, cols tx*4+j
            float sv[4][4] = {};
            #pragma unroll
            for (int kk = 0; kk < 32; kk++) {
                float4 a = *(const float4*)&QsT[kk][ty * 4];
                float4 b = *(const float4*)&KsT[kk][tx * 4];
                sv[0][0] = fmaf(a.x, b.x, sv[0][0]);
                sv[0][1] = fmaf(a.x, b.y, sv[0][1]);
                sv[0][2] = fmaf(a.x, b.z, sv[0][2]);
                sv[0][3] = fmaf(a.x, b.w, sv[0][3]);
                sv[1][0] = fmaf(a.y, b.x, sv[1][0]);
                sv[1][1] = fmaf(a.y, b.y, sv[1][1]);
                sv[1][2] = fmaf(a.y, b.z, sv[1][2]);
                sv[1][3] = fmaf(a.y, b.w, sv[1][3]);
                sv[2][0] = fmaf(a.z, b.x, sv[2][0]);
                sv[2][1] = fmaf(a.z, b.y, sv[2][1]);
                sv[2][2] = fmaf(a.z, b.z, sv[2][2]);
                sv[2][3] = fmaf(a.z, b.w, sv[2][3]);
                sv[3][0] = fmaf(a.w, b.x, sv[3][0]);
                sv[3][1] = fmaf(a.w, b.y, sv[3][1]);
                sv[3][2] = fmaf(a.w, b.z, sv[3][2]);
                sv[3][3] = fmaf(a.w, b.w, sv[3][3]);
            }

            // exp (bounded -> no max subtraction), per-row partial sums, W store
            int cb = s0 + tx * 4;
            #pragma unroll
            for (int i = 0; i < 4; i++) {
                float4 w;
                w.x = (cb + 0 >= ss && cb + 0 < se) ? fexp2(sv[i][0]) : 0.0f;
                w.y = (cb + 1 >= ss && cb + 1 < se) ? fexp2(sv[i][1]) : 0.0f;
                w.z = (cb + 2 >= ss && cb + 2 < se) ? fexp2(sv[i][2]) : 0.0f;
                w.w = (cb + 3 >= ss && cb + 3 < se) ? fexp2(sv[i][3]) : 0.0f;
                lpart[i] += (w.x + w.y) + (w.z + w.w);
                *(float4*)&Ws[ty * 4 + i][tx * 4] = w;
            }
            __syncthreads();

            // O accumulate: acc[seg] += Ws @ Vs  (float2 loads, R6-proven)
            #pragma unroll 8
            for (int s = 0; s < 64; s += 2) {
                float2 va = *(const float2*)&Vs[h2][s];
                float2 vbp = *(const float2*)&Vs[h2 + 1][s];
                #pragma unroll
                for (int k = 0; k < 4; k++) {
                    float2 w = *(const float2*)&Ws[ty + 16 * k][s];
                    acc[seg][k][0] = fmaf(w.y, va.y, fmaf(w.x, va.x, acc[seg][k][0]));
                    acc[seg][k][1] = fmaf(w.y, vbp.y, fmaf(w.x, vbp.x, acc[seg][k][1]));
                }
            }
        }
        // reduce per-row l across the 16 column-threads (width-16 shuffle)
        #pragma unroll
        for (int i = 0; i < 4; i++) {
            float lf = lpart[i];
            #pragma unroll
            for (int o = 8; o; o >>= 1)
                lf += __shfl_xor_sync(0xffffffffu, lf, o, 16);
            if (tx == 0) sl_s[seg][ty * 4 + i] = lf;
        }
    }
    __syncthreads();

    // per-row reciprocal denominators for all 7 branches (once)
    if (tid < 64) {
        float lr[3] = {sl_s[0][tid], sl_s[1][tid], sl_s[2][tid]};
        #pragma unroll
        for (int br = 0; br < 7; br++) {
            int mask = bmask[br];
            float den = 0.0f;
            #pragma unroll
            for (int s = 0; s < 3; s++)
                if ((mask >> s) & 1) den += lr[s];
            srd[br][tid] = __frcp_rn(den);
        }
    }
    __syncthreads();

    // combine: 7 branch outputs straight from registers
    #pragma unroll
    for (int k = 0; k < 4; k++) {
        int r = ty + 16 * k;
        int t = t0 + r;
        int seg_t = (t < 300) ? 0 : (t < 550) ? 1 : 2;
        #pragma unroll
        for (int br = 0; br < 7; br++) {
            int mask = bmask[br];
            float2 val = make_float2(0.0f, 0.0f);
            if ((mask >> seg_t) & 1) {
                float num0 = 0.0f, num1 = 0.0f;
                #pragma unroll
                for (int s = 0; s < 3; s++) {
                    if ((mask >> s) & 1) {
                        num0 += acc[s][k][0];
                        num1 += acc[s][k][1];
                    }
                }
                float rd = srd[br][r];
                val.x = num0 * rd;
                val.y = num1 * rd;
            }
            *(float2*)&g_obuf[(size_t)br * 786432 + (size_t)bh * 24576 +
                              (size_t)t * 32 + h2] = val;
        }
    }
}

// ---------------- build G_i = sums of s_*_w column blocks ----------------
__global__ void __launch_bounds__(256) gmat_kernel(
    const float* __restrict__ sl, const float* __restrict__ sa,
    const float* __restrict__ sv)
{
    int idx = blockIdx.x * 256 + threadIdx.x;
    int i = idx >> 16;
    int y = (idx >> 8) & 255;
    int x = idx & 255;
    size_t r = (size_t)y * 1024;
    float v = 0.0f;
    switch (i) {
        case 0: v = sl[r + x]       + sa[r + x]       + sv[r + x];   break;
        case 1: v = sl[r + 256 + x] + sa[r + 256 + x];               break;
        case 2: v = sl[r + 512 + x] + sv[r + 256 + x];               break;
        case 3: v = sa[r + 512 + x] + sv[r + 512 + x];               break;
        case 4: v = sl[r + 768 + x];                                 break;
        case 5: v = sa[r + 768 + x];                                 break;
        case 6: v = sv[r + 768 + x];                                 break;
    }
    g_G[idx] = v;
}

// ---------------- bias fold, stage 1 ----------------
__global__ void __launch_bounds__(256) bias1_kernel(
    const float* __restrict__ out_b, const float* __restrict__ slb,
    const float* __restrict__ sab, const float* __restrict__ svb)
{
    int y = blockIdx.x;
    int tid = threadIdx.x;
    __shared__ float red[256];
    float p = 0.0f;
    #pragma unroll
    for (int i = 0; i < 7; i++)
        p += out_b[i * 256 + tid] * g_G[i * 65536 + y * 256 + tid];
    red[tid] = p;
    __syncthreads();
    for (int o = 128; o; o >>= 1) {
        if (tid < o) red[tid] += red[tid + o];
        __syncthreads();
    }
    if (tid == 0) g_c1[y] = red[0] + slb[y] + sab[y] + svb[y];
}

// ---------------- bias fold, stage 2 ----------------
__global__ void __launch_bounds__(256) bias2_kernel(
    const float* __restrict__ fb, const float* __restrict__ fw)
{
    int n = blockIdx.x;
    int tid = threadIdx.x;
    __shared__ float red[256];
    red[tid] = g_c1[tid] * fw[(size_t)n * 256 + tid];
    __syncthreads();
    for (int o = 128; o; o >>= 1) {
        if (tid < o) red[tid] += red[tid + o];
        __syncthreads();
    }
    if (tid == 0) g_biasv[n] = red[0] + fb[n];
}

// ---------------- final fused GEMM: out = sum_i o_i @ M_i + bias (dead-branch skip) ----------------
__global__ void __launch_bounds__(256) final_kernel(float* __restrict__ out)
{
    int m0 = blockIdx.y * 64, n0 = blockIdx.x * 32;
    __shared__ float As[32][68], Bs[32][36];
    int tid = threadIdx.x;
    int tx = tid & 15, ty = tid >> 4;

    int tb0 = m0 >> 2, tb1 = (m0 + 63) >> 2;
    int bm = 0;
    #pragma unroll
    for (int br = 0; br < 7; br++) {
        int mk = c_bmask[br];
        #pragma unroll
        for (int s = 0; s < 3; s++)
            if (((mk >> s) & 1) && tb0 < c_segE[s] && tb1 >= c_segS[s]) bm |= 1 << br;
    }

    float acc[4][2] = {};
    for (int k0 = 0; k0 < 1792; k0 += 32) {
        int ibr = k0 >> 8;
        if (!((bm >> ibr) & 1)) continue;
        int h = (k0 & 255) >> 5;
        const float* Abase = g_obuf + (size_t)ibr * 786432 + (size_t)h * 24576;
        #pragma unroll
        for (int i = 0; i < 8; i++) {
            int idx = tid + i * 256;
            int mm = idx >> 5, kk = idx & 31;
            int m = m0 + mm;
            int t = m >> 2, b = m & 3;
            As[kk][mm] = Abase[(size_t)b * 196608 + (size_t)t * 32 + kk];
        }
        #pragma unroll
        for (int i = 0; i < 4; i++) {
            int idx = tid + i * 256;
            int nn = idx >> 5, kk = idx & 31;
            Bs[kk][nn] = g_MTcat[(size_t)(n0 + nn) * 1792 + k0 + kk];
        }
        __syncthreads();
        #pragma unroll
        for (int kk = 0; kk < 32; kk++) {
            float4 a = *(const float4*)&As[kk][ty * 4];
            float2 b = *(const float2*)&Bs[kk][tx * 2];
            acc[0][0] = fmaf(a.x, b.x, acc[0][0]);
            acc[0][1] = fmaf(a.x, b.y, acc[0][1]);
            acc[1][0] = fmaf(a.y, b.x, acc[1][0]);
            acc[1][1] = fmaf(a.y, b.y, acc[1][1]);
            acc[2][0] = fmaf(a.z, b.x, acc[2][0]);
            acc[2][1] = fmaf(a.z, b.y, acc[2][1]);
            acc[3][0] = fmaf(a.w, b.x, acc[3][0]);
            acc[3][1] = fmaf(a.w, b.y, acc[3][1]);
        }
        __syncthreads();
    }
    #pragma unroll
    for (int i = 0; i < 4; i++) {
        int m = m0 + ty * 4 + i;
        #pragma unroll
        for (int j = 0; j < 2; j++) {
            int n = n0 + tx * 2 + j;
            out[(size_t)m * 256 + n] = acc[i][j] + g_biasv[n];
        }
    }
}

// ---------------- launch (serial; flash kept as 4th launch for ncu) ----------------
extern "C" void kernel_launch(void* const* d_in, const int* in_sizes, int n_in,
                              void* d_out, int out_size)
{
    const float* query     = (const float*)d_in[0];
    const float* key       = (const float*)d_in[1];
    const float* value     = (const float*)d_in[2];
    const float* in_proj_w = (const float*)d_in[3];
    const float* in_proj_b = (const float*)d_in[4];
    const float* out_w     = (const float*)d_in[5];
    const float* out_b     = (const float*)d_in[6];
    const float* s_l_w     = (const float*)d_in[7];
    const float* s_l_b     = (const float*)d_in[8];
    const float* s_a_w     = (const float*)d_in[9];
    const float* s_a_b     = (const float*)d_in[10];
    const float* s_v_w     = (const float*)d_in[11];
    const float* s_v_b     = (const float*)d_in[12];
    const float* final_w   = (const float*)d_in[13];
    const float* final_b   = (const float*)d_in[14];
    float* out = (float*)d_out;
    (void)in_sizes; (void)n_in; (void)out_size;

    float *p_G, *p_tmpT, *p_MTcat;
    cudaGetSymbolAddress((void**)&p_G,      g_G);
    cudaGetSymbolAddress((void**)&p_tmpT,   g_tmpT);
    cudaGetSymbolAddress((void**)&p_MTcat,  g_MTcat);

    // launch #1: q/k/v projections -> head-major
    proj_kernel<<<dim3(4, 48, 3), 256>>>(query, key, value, in_proj_w, in_proj_b);

    // launch #2: G_i (weights only)
    gmat_kernel<<<1792, 256>>>(s_l_w, s_a_w, s_v_w);

    // launch #3: tmpT[i][a][y] = sum_x out_w[i][x][a] * G_i[y][x]
    gemm_small<<<dim3(8, 8, 7), 256>>>(
        out_w, 1, 256, 65536,
        p_G, 256, 1, 65536,
        p_tmpT, 256, 65536, 256);

    // launch #4: fused flash attention + branch combine  (ncu profiles this one)
    flash_kernel<<<dim3(12, 32), 256>>>();

    // launch #5: MTcat[n][i*256+a] = sum_y final_w[n][y] * tmpT[i][a][y]
    gemm_small<<<dim3(8, 8, 7), 256>>>(
        final_w, 256, 1, 0,
        p_tmpT, 256, 1, 65536,
        p_MTcat, 1792, 256, 256);

    // launches #6,#7: fold biases
    bias1_kernel<<<256, 256>>>(out_b, s_l_b, s_a_b, s_v_b);
    bias2_kernel<<<256, 256>>>(final_b, final_w);

    // launch #8: out = sum_i o_i @ M_i + bias
    final_kernel<<<dim3(8, 48), 256>>>(out);
}

// round 15
// speedup vs baseline: 1.2015x; 1.0009x over previous
#include <cuda_runtime.h>
#include <cuda_fp16.h>
#include <math.h>
#include <stdint.h>

// Problem constants: T=768, B=4, E=256, H=8, HD=32, 32 "bh" heads.
// Q scale folded with log2(e): scores arrive in log2 domain, exp(s) == 2^s'.
#define QSCALE 0.25500917392938054f   // (1/sqrt(32)) * log2(e)

// ---------------- scratch (static device globals; no allocation) ----------------
__device__ float g_q[786432];        // [bh=32][t=768][hd=32]
__device__ float g_k[786432];
__device__ float g_v[786432];
__device__ float g_obuf[5505024];    // [branch=7][bh=32][t=768][hd=32]
__device__ float g_G[458752];        // [7][y=256][x=256]
__device__ float g_tmpT[458752];     // [7][a=256][y=256]
__device__ float g_MTcat[458752];    // [n=256][k=1792]
__device__ float g_c1[256];
__device__ float g_biasv[256];

// Segments partition the columns: L=[0,300) A=[300,550) V=[550,768)
__constant__ int c_segS[3] = {0, 300, 550};
__constant__ int c_segE[3] = {300, 550, 768};
// branch -> segment bitmask: lav, la, lv, av, l, a, v
__constant__ int c_bmask[7] = {7, 3, 5, 6, 1, 2, 4};

// bit-cast helpers (no SASS cost)
__device__ __forceinline__ uint32_t h2_as_u32(__half2 h) {
    return *reinterpret_cast<uint32_t*>(&h);
}
__device__ __forceinline__ __half2 u32_as_h2(uint32_t u) {
    return *reinterpret_cast<__half2*>(&u);
}

// FMA-pipe 2^x (no MUFU). |x| < ~80, rel err ~1e-7 (deg-6 Taylor on [-0.5,0.5]).
__device__ __forceinline__ float fexp2(float x)
{
    float z = x + 12582912.0f;            // 1.5*2^23: round-to-nearest-int trick
    int   n = __float_as_int(z);          // low bits hold round(x)
    float f = x - (z - 12582912.0f);      // frac in [-0.5, 0.5], exact
    float p = 1.5402387e-4f;
    p = fmaf(p, f, 1.3333558e-3f);
    p = fmaf(p, f, 9.6181291e-3f);
    p = fmaf(p, f, 5.5504109e-2f);
    p = fmaf(p, f, 2.4022651e-1f);
    p = fmaf(p, f, 6.9314718e-1f);
    p = fmaf(p, f, 1.0f);
    return __int_as_float(__float_as_int(p) + (n << 23));
}

// ---------------- small tiled SGEMM (32x32 tiles, K-step 32), coalesced ----------------
__global__ void __launch_bounds__(256) gemm_small(
    const float* __restrict__ A, int a_sm, int a_sk, int a_bz,
    const float* __restrict__ B, int b_sn, int b_sk, int b_bz,
    float* __restrict__ C, int c_sm, int c_bz,
    int K)
{
    A += (size_t)blockIdx.z * a_bz;
    B += (size_t)blockIdx.z * b_bz;
    C += (size_t)blockIdx.z * c_bz;
    int m0 = blockIdx.y * 32, n0 = blockIdx.x * 32;
    __shared__ float As[32][36], Bs[32][36];
    int tid = threadIdx.x;
    int tx = tid & 15, ty = tid >> 4;
    float acc[2][2] = {};
    for (int k0 = 0; k0 < K; k0 += 32) {
        if (a_sk == 1) {   // k contiguous: kk fastest across tid
            #pragma unroll
            for (int i = 0; i < 4; i++) {
                int idx = tid + i * 256;
                int mm = idx >> 5, kk = idx & 31;
                As[kk][mm] = A[(size_t)(m0 + mm) * a_sm + (k0 + kk)];
            }
        } else {           // m contiguous: mm fastest across tid
            #pragma unroll
            for (int i = 0; i < 4; i++) {
                int idx = tid + i * 256;
                int mm = idx & 31, kk = idx >> 5;
                As[kk][mm] = A[(size_t)(m0 + mm) + (size_t)(k0 + kk) * a_sk];
            }
        }
        if (b_sk == 1) {
            #pragma unroll
            for (int i = 0; i < 4; i++) {
                int idx = tid + i * 256;
                int mm = idx >> 5, kk = idx & 31;
                Bs[kk][mm] = B[(size_t)(n0 + mm) * b_sn + (k0 + kk)];
            }
        } else {
            #pragma unroll
            for (int i = 0; i < 4; i++) {
                int idx = tid + i * 256;
                int mm = idx & 31, kk = idx >> 5;
                Bs[kk][mm] = B[(size_t)(n0 + mm) + (size_t)(k0 + kk) * b_sk];
            }
        }
        __syncthreads();
        #pragma unroll
        for (int kk = 0; kk < 32; kk++) {
            float2 a = *(const float2*)&As[kk][ty * 2];
            float2 b = *(const float2*)&Bs[kk][tx * 2];
            acc[0][0] = fmaf(a.x, b.x, acc[0][0]);
            acc[0][1] = fmaf(a.x, b.y, acc[0][1]);
            acc[1][0] = fmaf(a.y, b.x, acc[1][0]);
            acc[1][1] = fmaf(a.y, b.y, acc[1][1]);
        }
        __syncthreads();
    }
    #pragma unroll
    for (int i = 0; i < 2; i++)
        #pragma unroll
        for (int j = 0; j < 2; j++)
            C[(size_t)(m0 + ty * 2 + i) * c_sm + (n0 + tx * 2 + j)] = acc[i][j];
}

// ---------------- QKV projection, scattered to head-major ----------------
__global__ void __launch_bounds__(256) proj_kernel(
    const float* __restrict__ q_in, const float* __restrict__ k_in,
    const float* __restrict__ v_in, const float* __restrict__ W,
    const float* __restrict__ bias)
{
    int z = blockIdx.z;
    const float* A = (z == 0) ? q_in : (z == 1) ? k_in : v_in;
    float* dst = (z == 0) ? g_q : (z == 1) ? g_k : g_v;
    const float* Bw = W + (size_t)z * 65536;
    const float* bz = bias + z * 256;
    float scale = (z == 0) ? QSCALE : 1.0f;

    int m0 = blockIdx.y * 64, n0 = blockIdx.x * 64;
    __shared__ float As[16][68], Bs[16][68];
    int tid = threadIdx.x;
    int tx = tid & 15, ty = tid >> 4;
    float acc[4][4] = {};
    for (int k0 = 0; k0 < 256; k0 += 16) {
        #pragma unroll
        for (int i = 0; i < 4; i++) {
            int idx = tid + i * 256;
            int mm = idx >> 4, kk = idx & 15;
            As[kk][mm] = A[(size_t)(m0 + mm) * 256 + (k0 + kk)];
            Bs[kk][mm] = Bw[(size_t)(n0 + mm) * 256 + (k0 + kk)];
        }
        __syncthreads();
        #pragma unroll
        for (int kk = 0; kk < 16; kk++) {
            float4 a = *(const float4*)&As[kk][ty * 4];
            float4 b = *(const float4*)&Bs[kk][tx * 4];
            acc[0][0] = fmaf(a.x, b.x, acc[0][0]);
            acc[0][1] = fmaf(a.x, b.y, acc[0][1]);
            acc[0][2] = fmaf(a.x, b.z, acc[0][2]);
            acc[0][3] = fmaf(a.x, b.w, acc[0][3]);
            acc[1][0] = fmaf(a.y, b.x, acc[1][0]);
            acc[1][1] = fmaf(a.y, b.y, acc[1][1]);
            acc[1][2] = fmaf(a.y, b.z, acc[1][2]);
            acc[1][3] = fmaf(a.y, b.w, acc[1][3]);
            acc[2][0] = fmaf(a.z, b.x, acc[2][0]);
            acc[2][1] = fmaf(a.z, b.y, acc[2][1]);
            acc[2][2] = fmaf(a.z, b.z, acc[2][2]);
            acc[2][3] = fmaf(a.z, b.w, acc[2][3]);
            acc[3][0] = fmaf(a.w, b.x, acc[3][0]);
            acc[3][1] = fmaf(a.w, b.y, acc[3][1]);
            acc[3][2] = fmaf(a.w, b.z, acc[3][2]);
            acc[3][3] = fmaf(a.w, b.w, acc[3][3]);
        }
        __syncthreads();
    }
    #pragma unroll
    for (int i = 0; i < 4; i++) {
        int m = m0 + ty * 4 + i;
        int t = m >> 2, b = m & 3;
        #pragma unroll
        for (int j = 0; j < 4; j++) {
            int n = n0 + tx * 4 + j;
            int h = n >> 5, hd = n & 31;
            float val = (acc[i][j] + bz[n]) * scale;
            dst[(size_t)((b * 8 + h) * 768 + t) * 32 + hd] = val;
        }
    }
}

// ---------------- fully fused flash attention + branch combine ----------------
// Occupancy-forced (3 CTAs/SM). W and V staged in smem as half2 -> PV smem
// bytes and LDS issue count halved (L1 was at 71.5%); fp32 accumulate.
__global__ void __launch_bounds__(256, 3) flash_kernel()
{
    const int segS[3] = {0, 300, 550};
    const int segE[3] = {300, 550, 768};
    const int bmask[7] = {7, 3, 5, 6, 1, 2, 4};

    int bh = blockIdx.y, t0 = blockIdx.x * 64;
    int tid = threadIdx.x;
    int tx = tid & 15, ty = tid >> 4;   // S mapping: rows ty*4+i, cols tx*4+j
    int h2 = tx * 2;                    // PV mapping: rows ty+16k, hd pair h2

    __shared__ float QsT[32][68], KsT[32][68];
    __shared__ __half2 Wsh[64][34];     // [row][col pair]
    __shared__ __half2 Vsh[32][34];     // [hd][col pair]
    __shared__ float sl_s[3][64];
    __shared__ float srd[7][64];

    const float* qbase = g_q + (size_t)bh * 24576 + (size_t)t0 * 32;
    const float* kb = g_k + (size_t)bh * 24576;
    const float* vb = g_v + (size_t)bh * 24576;

    #pragma unroll
    for (int i = 0; i < 8; i++) {
        int idx = tid + i * 256;
        int r = idx >> 5, kk = idx & 31;
        QsT[kk][r] = qbase[r * 32 + kk];
    }

    float acc[3][4][2] = {};

    #pragma unroll
    for (int seg = 0; seg < 3; seg++) {
        int ss = segS[seg], se = segE[seg];
        int ts = ss >> 6, te = (se + 63) >> 6;
        float lpart[4];
        #pragma unroll
        for (int i = 0; i < 4; i++) lpart[i] = 0.0f;

        for (int st = ts; st < te; st++) {
            int s0 = st * 64;
            __syncthreads();
            #pragma unroll
            for (int i = 0; i < 8; i++) {
                int idx = tid + i * 256;
                int r = idx >> 5, kk = idx & 31;
                KsT[kk][r] = kb[(size_t)(s0 + r) * 32 + kk];
            }
            // V tile -> half2, transposed: Vsh[hd][sc2] = (v[2sc2][hd], v[2sc2+1][hd])
            #pragma unroll
            for (int i = 0; i < 4; i++) {
                int idx = tid + i * 256;          // 0..1023
                int sc2 = idx >> 5, hd = idx & 31;
                float v0 = vb[(size_t)(s0 + 2 * sc2) * 32 + hd];
                float v1 = vb[(size_t)(s0 + 2 * sc2 + 1) * 32 + hd];
                Vsh[hd][sc2] = __floats2half2_rn(v0, v1);
            }
            __syncthreads();

            // S tile 4x4: rows ty*4+i, cols tx*4+j
            float sv[4][4] = {};
            #pragma unroll
            for (int kk = 0; kk < 32; kk++) {
                float4 a = *(const float4*)&QsT[kk][ty * 4];
                float4 b = *(const float4*)&KsT[kk][tx * 4];
                sv[0][0] = fmaf(a.x, b.x, sv[0][0]);
                sv[0][1] = fmaf(a.x, b.y, sv[0][1]);
                sv[0][2] = fmaf(a.x, b.z, sv[0][2]);
                sv[0][3] = fmaf(a.x, b.w, sv[0][3]);
                sv[1][0] = fmaf(a.y, b.x, sv[1][0]);
                sv[1][1] = fmaf(a.y, b.y, sv[1][1]);
                sv[1][2] = fmaf(a.y, b.z, sv[1][2]);
                sv[1][3] = fmaf(a.y, b.w, sv[1][3]);
                sv[2][0] = fmaf(a.z, b.x, sv[2][0]);
                sv[2][1] = fmaf(a.z, b.y, sv[2][1]);
                sv[2][2] = fmaf(a.z, b.z, sv[2][2]);
                sv[2][3] = fmaf(a.z, b.w, sv[2][3]);
                sv[3][0] = fmaf(a.w, b.x, sv[3][0]);
                sv[3][1] = fmaf(a.w, b.y, sv[3][1]);
                sv[3][2] = fmaf(a.w, b.z, sv[3][2]);
                sv[3][3] = fmaf(a.w, b.w, sv[3][3]);
            }

            // exp (bounded), per-row partial sums (fp32, pre-round), half2 W store
            int cb = s0 + tx * 4;
            #pragma unroll
            for (int i = 0; i < 4; i++) {
                float w0 = (cb + 0 >= ss && cb + 0 < se) ? fexp2(sv[i][0]) : 0.0f;
                float w1 = (cb + 1 >= ss && cb + 1 < se) ? fexp2(sv[i][1]) : 0.0f;
                float w2 = (cb + 2 >= ss && cb + 2 < se) ? fexp2(sv[i][2]) : 0.0f;
                float w3 = (cb + 3 >= ss && cb + 3 < se) ? fexp2(sv[i][3]) : 0.0f;
                lpart[i] += (w0 + w1) + (w2 + w3);
                __half2 p0 = __floats2half2_rn(w0, w1);
                __half2 p1 = __floats2half2_rn(w2, w3);
                // two half2 = 8B aligned store (tx*2 even)
                *(uint2*)&Wsh[ty * 4 + i][tx * 2] =
                    make_uint2(h2_as_u32(p0), h2_as_u32(p1));
            }
            __syncthreads();

            // O accumulate: acc[seg] += W @ V  (uint2 = 4 halves per LDS.64)
            #pragma unroll 4
            for (int s2 = 0; s2 < 32; s2 += 2) {    // covers cols 2*s2..2*s2+3
                uint2 vha = *(const uint2*)&Vsh[h2][s2];
                uint2 vhb = *(const uint2*)&Vsh[h2 + 1][s2];
                float2 va01 = __half22float2(u32_as_h2(vha.x));
                float2 va23 = __half22float2(u32_as_h2(vha.y));
                float2 vb01 = __half22float2(u32_as_h2(vhb.x));
                float2 vb23 = __half22float2(u32_as_h2(vhb.y));
                #pragma unroll
                for (int k = 0; k < 4; k++) {
                    uint2 wh = *(const uint2*)&Wsh[ty + 16 * k][s2];
                    float2 w01 = __half22float2(u32_as_h2(wh.x));
                    float2 w23 = __half22float2(u32_as_h2(wh.y));
                    acc[seg][k][0] = fmaf(w23.y, va23.y, fmaf(w23.x, va23.x,
                                     fmaf(w01.y, va01.y, fmaf(w01.x, va01.x, acc[seg][k][0]))));
                    acc[seg][k][1] = fmaf(w23.y, vb23.y, fmaf(w23.x, vb23.x,
                                     fmaf(w01.y, vb01.y, fmaf(w01.x, vb01.x, acc[seg][k][1]))));
                }
            }
        }
        // reduce per-row l across the 16 column-threads (width-16 shuffle)
        #pragma unroll
        for (int i = 0; i < 4; i++) {
            float lf = lpart[i];
            #pragma unroll
            for (int o = 8; o; o >>= 1)
                lf += __shfl_xor_sync(0xffffffffu, lf, o, 16);
            if (tx == 0) sl_s[seg][ty * 4 + i] = lf;
        }
    }
    __syncthreads();

    // per-row reciprocal denominators for all 7 branches (once)
    if (tid < 64) {
        float lr[3] = {sl_s[0][tid], sl_s[1][tid], sl_s[2][tid]};
        #pragma unroll
        for (int br = 0; br < 7; br++) {
            int mask = bmask[br];
            float den = 0.0f;
            #pragma unroll
            for (int s = 0; s < 3; s++)
                if ((mask >> s) & 1) den += lr[s];
            srd[br][tid] = __frcp_rn(den);
        }
    }
    __syncthreads();

    // combine: 7 branch outputs straight from registers
    #pragma unroll
    for (int k = 0; k < 4; k++) {
        int r = ty + 16 * k;
        int t = t0 + r;
        int seg_t = (t < 300) ? 0 : (t < 550) ? 1 : 2;
        #pragma unroll
        for (int br = 0; br < 7; br++) {
            int mask = bmask[br];
            float2 val = make_float2(0.0f, 0.0f);
            if ((mask >> seg_t) & 1) {
                float num0 = 0.0f, num1 = 0.0f;
                #pragma unroll
                for (int s = 0; s < 3; s++) {
                    if ((mask >> s) & 1) {
                        num0 += acc[s][k][0];
                        num1 += acc[s][k][1];
                    }
                }
                float rd = srd[br][r];
                val.x = num0 * rd;
                val.y = num1 * rd;
            }
            *(float2*)&g_obuf[(size_t)br * 786432 + (size_t)bh * 24576 +
                              (size_t)t * 32 + h2] = val;
        }
    }
}

// ---------------- build G_i = sums of s_*_w column blocks ----------------
__global__ void __launch_bounds__(256) gmat_kernel(
    const float* __restrict__ sl, const float* __restrict__ sa,
    const float* __restrict__ sv)
{
    int idx = blockIdx.x * 256 + threadIdx.x;
    int i = idx >> 16;
    int y = (idx >> 8) & 255;
    int x = idx & 255;
    size_t r = (size_t)y * 1024;
    float v = 0.0f;
    switch (i) {
        case 0: v = sl[r + x]       + sa[r + x]       + sv[r + x];   break;
        case 1: v = sl[r + 256 + x] + sa[r + 256 + x];               break;
        case 2: v = sl[r + 512 + x] + sv[r + 256 + x];               break;
        case 3: v = sa[r + 512 + x] + sv[r + 512 + x];               break;
        case 4: v = sl[r + 768 + x];                                 break;
        case 5: v = sa[r + 768 + x];                                 break;
        case 6: v = sv[r + 768 + x];                                 break;
    }
    g_G[idx] = v;
}

// ---------------- bias fold, stage 1 ----------------
__global__ void __launch_bounds__(256) bias1_kernel(
    const float* __restrict__ out_b, const float* __restrict__ slb,
    const float* __restrict__ sab, const float* __restrict__ svb)
{
    int y = blockIdx.x;
    int tid = threadIdx.x;
    __shared__ float red[256];
    float p = 0.0f;
    #pragma unroll
    for (int i = 0; i < 7; i++)
        p += out_b[i * 256 + tid] * g_G[i * 65536 + y * 256 + tid];
    red[tid] = p;
    __syncthreads();
    for (int o = 128; o; o >>= 1) {
        if (tid < o) red[tid] += red[tid + o];
        __syncthreads();
    }
    if (tid == 0) g_c1[y] = red[0] + slb[y] + sab[y] + svb[y];
}

// ---------------- bias fold, stage 2 ----------------
__global__ void __launch_bounds__(256) bias2_kernel(
    const float* __restrict__ fb, const float* __restrict__ fw)
{
    int n = blockIdx.x;
    int tid = threadIdx.x;
    __shared__ float red[256];
    red[tid] = g_c1[tid] * fw[(size_t)n * 256 + tid];
    __syncthreads();
    for (int o = 128; o; o >>= 1) {
        if (tid < o) red[tid] += red[tid + o];
        __syncthreads();
    }
    if (tid == 0) g_biasv[n] = red[0] + fb[n];
}

// ---------------- final fused GEMM: out = sum_i o_i @ M_i + bias (dead-branch skip) ----------------
__global__ void __launch_bounds__(256) final_kernel(float* __restrict__ out)
{
    int m0 = blockIdx.y * 64, n0 = blockIdx.x * 32;
    __shared__ float As[32][68], Bs[32][36];
    int tid = threadIdx.x;
    int tx = tid & 15, ty = tid >> 4;

    int tb0 = m0 >> 2, tb1 = (m0 + 63) >> 2;
    int bm = 0;
    #pragma unroll
    for (int br = 0; br < 7; br++) {
        int mk = c_bmask[br];
        #pragma unroll
        for (int s = 0; s < 3; s++)
            if (((mk >> s) & 1) && tb0 < c_segE[s] && tb1 >= c_segS[s]) bm |= 1 << br;
    }

    float acc[4][2] = {};
    for (int k0 = 0; k0 < 1792; k0 += 32) {
        int ibr = k0 >> 8;
        if (!((bm >> ibr) & 1)) continue;
        int h = (k0 & 255) >> 5;
        const float* Abase = g_obuf + (size_t)ibr * 786432 + (size_t)h * 24576;
        #pragma unroll
        for (int i = 0; i < 8; i++) {
            int idx = tid + i * 256;
            int mm = idx >> 5, kk = idx & 31;
            int m = m0 + mm;
            int t = m >> 2, b = m & 3;
            As[kk][mm] = Abase[(size_t)b * 196608 + (size_t)t * 32 + kk];
        }
        #pragma unroll
        for (int i = 0; i < 4; i++) {
            int idx = tid + i * 256;
            int nn = idx >> 5, kk = idx & 31;
            Bs[kk][nn] = g_MTcat[(size_t)(n0 + nn) * 1792 + k0 + kk];
        }
        __syncthreads();
        #pragma unroll
        for (int kk = 0; kk < 32; kk++) {
            float4 a = *(const float4*)&As[kk][ty * 4];
            float2 b = *(const float2*)&Bs[kk][tx * 2];
            acc[0][0] = fmaf(a.x, b.x, acc[0][0]);
            acc[0][1] = fmaf(a.x, b.y, acc[0][1]);
            acc[1][0] = fmaf(a.y, b.x, acc[1][0]);
            acc[1][1] = fmaf(a.y, b.y, acc[1][1]);
            acc[2][0] = fmaf(a.z, b.x, acc[2][0]);
            acc[2][1] = fmaf(a.z, b.y, acc[2][1]);
            acc[3][0] = fmaf(a.w, b.x, acc[3][0]);
            acc[3][1] = fmaf(a.w, b.y, acc[3][1]);
        }
        __syncthreads();
    }
    #pragma unroll
    for (int i = 0; i < 4; i++) {
        int m = m0 + ty * 4 + i;
        #pragma unroll
        for (int j = 0; j < 2; j++) {
            int n = n0 + tx * 2 + j;
            out[(size_t)m * 256 + n] = acc[i][j] + g_biasv[n];
        }
    }
}

// ---------------- launch (serial; flash kept as 4th launch for ncu) ----------------
extern "C" void kernel_launch(void* const* d_in, const int* in_sizes, int n_in,
                              void* d_out, int out_size)
{
    const float* query     = (const float*)d_in[0];
    const float* key       = (const float*)d_in[1];
    const float* value     = (const float*)d_in[2];
    const float* in_proj_w = (const float*)d_in[3];
    const float* in_proj_b = (const float*)d_in[4];
    const float* out_w     = (const float*)d_in[5];
    const float* out_b     = (const float*)d_in[6];
    const float* s_l_w     = (const float*)d_in[7];
    const float* s_l_b     = (const float*)d_in[8];
    const float* s_a_w     = (const float*)d_in[9];
    const float* s_a_b     = (const float*)d_in[10];
    const float* s_v_w     = (const float*)d_in[11];
    const float* s_v_b     = (const float*)d_in[12];
    const float* final_w   = (const float*)d_in[13];
    const float* final_b   = (const float*)d_in[14];
    float* out = (float*)d_out;
    (void)in_sizes; (void)n_in; (void)out_size;

    float *p_G, *p_tmpT, *p_MTcat;
    cudaGetSymbolAddress((void**)&p_G,      g_G);
    cudaGetSymbolAddress((void**)&p_tmpT,   g_tmpT);
    cudaGetSymbolAddress((void**)&p_MTcat,  g_MTcat);

    // launch #1: q/k/v projections -> head-major
    proj_kernel<<<dim3(4, 48, 3), 256>>>(query, key, value, in_proj_w, in_proj_b);

    // launch #2: G_i (weights only)
    gmat_kernel<<<1792, 256>>>(s_l_w, s_a_w, s_v_w);

    // launch #3: tmpT[i][a][y] = sum_x out_w[i][x][a] * G_i[y][x]
    gemm_small<<<dim3(8, 8, 7), 256>>>(
        out_w, 1, 256, 65536,
        p_G, 256, 1, 65536,
        p_tmpT, 256, 65536, 256);

    // launch #4: fused flash attention + branch combine  (ncu profiles this one)
    flash_kernel<<<dim3(12, 32), 256>>>();

    // launch #5: MTcat[n][i*256+a] = sum_y final_w[n][y] * tmpT[i][a][y]
    gemm_small<<<dim3(8, 8, 7), 256>>>(
        final_w, 256, 1, 0,
        p_tmpT, 256, 1, 65536,
        p_MTcat, 1792, 256, 256);

    // launches #6,#7: fold biases
    bias1_kernel<<<256, 256>>>(out_b, s_l_b, s_a_b, s_v_b);
    bias2_kernel<<<256, 256>>>(final_b, final_w);

    // launch #8: out = sum_i o_i @ M_i + bias
    final_kernel<<<dim3(8, 48), 256>>>(out);
}

// round 16
// speedup vs baseline: 1.4126x; 1.1757x over previous
#include <cuda_runtime.h>
#include <cuda_fp16.h>
#include <math.h>
#include <stdint.h>

// Problem constants: T=768, B=4, E=256, H=8, HD=32, 32 "bh" heads.
// Q scale folded with log2(e): scores arrive in log2 domain, exp(s) == 2^s'.
#define QSCALE 0.25500917392938054f   // (1/sqrt(32)) * log2(e)

// ---------------- scratch (static device globals; no allocation) ----------------
__device__ float g_q[786432];        // [bh=32][t=768][hd=32]
__device__ float g_k[786432];
__device__ float g_v[786432];
__device__ float g_obuf[5505024];    // [branch=7][bh=32][t=768][hd=32]
__device__ float g_G[458752];        // [7][y=256][x=256]
__device__ float g_tmpT[458752];     // [7][a=256][y=256]
__device__ float g_MTcat[458752];    // [n=256][k=1792]
__device__ float g_c1[256];
__device__ float g_biasv[256];

// Segments partition the columns: L=[0,300) A=[300,550) V=[550,768)
__constant__ int c_segS[3] = {0, 300, 550};
__constant__ int c_segE[3] = {300, 550, 768};
// branch -> segment bitmask: lav, la, lv, av, l, a, v
__constant__ int c_bmask[7] = {7, 3, 5, 6, 1, 2, 4};

// bit-cast helpers (no SASS cost)
__device__ __forceinline__ uint32_t h2_as_u32(__half2 h) {
    return *reinterpret_cast<uint32_t*>(&h);
}

// FMA-pipe 2^x (no MUFU). |x| < ~80, rel err ~1e-7 (deg-6 Taylor on [-0.5,0.5]).
__device__ __forceinline__ float fexp2(float x)
{
    float z = x + 12582912.0f;            // 1.5*2^23: round-to-nearest-int trick
    int   n = __float_as_int(z);          // low bits hold round(x)
    float f = x - (z - 12582912.0f);      // frac in [-0.5, 0.5], exact
    float p = 1.5402387e-4f;
    p = fmaf(p, f, 1.3333558e-3f);
    p = fmaf(p, f, 9.6181291e-3f);
    p = fmaf(p, f, 5.5504109e-2f);
    p = fmaf(p, f, 2.4022651e-1f);
    p = fmaf(p, f, 6.9314718e-1f);
    p = fmaf(p, f, 1.0f);
    return __int_as_float(__float_as_int(p) + (n << 23));
}

// m16n8k16 f16 mma with fp32 accumulate (half x half products are exact in fp32)
__device__ __forceinline__ void mma_f16(float* c,
    uint32_t a0, uint32_t a1, uint32_t a2, uint32_t a3,
    uint32_t b0, uint32_t b1)
{
    asm volatile(
        "mma.sync.aligned.m16n8k16.row.col.f32.f16.f16.f32 "
        "{%0,%1,%2,%3}, {%4,%5,%6,%7}, {%8,%9}, {%0,%1,%2,%3};"
        : "+f"(c[0]), "+f"(c[1]), "+f"(c[2]), "+f"(c[3])
        : "r"(a0), "r"(a1), "r"(a2), "r"(a3), "r"(b0), "r"(b1));
}

// ---------------- small tiled SGEMM (32x32 tiles, K-step 32), coalesced ----------------
__global__ void __launch_bounds__(256) gemm_small(
    const float* __restrict__ A, int a_sm, int a_sk, int a_bz,
    const float* __restrict__ B, int b_sn, int b_sk, int b_bz,
    float* __restrict__ C, int c_sm, int c_bz,
    int K)
{
    A += (size_t)blockIdx.z * a_bz;
    B += (size_t)blockIdx.z * b_bz;
    C += (size_t)blockIdx.z * c_bz;
    int m0 = blockIdx.y * 32, n0 = blockIdx.x * 32;
    __shared__ float As[32][36], Bs[32][36];
    int tid = threadIdx.x;
    int tx = tid & 15, ty = tid >> 4;
    float acc[2][2] = {};
    for (int k0 = 0; k0 < K; k0 += 32) {
        if (a_sk == 1) {
            #pragma unroll
            for (int i = 0; i < 4; i++) {
                int idx = tid + i * 256;
                int mm = idx >> 5, kk = idx & 31;
                As[kk][mm] = A[(size_t)(m0 + mm) * a_sm + (k0 + kk)];
            }
        } else {
            #pragma unroll
            for (int i = 0; i < 4; i++) {
                int idx = tid + i * 256;
                int mm = idx & 31, kk = idx >> 5;
                As[kk][mm] = A[(size_t)(m0 + mm) + (size_t)(k0 + kk) * a_sk];
            }
        }
        if (b_sk == 1) {
            #pragma unroll
            for (int i = 0; i < 4; i++) {
                int idx = tid + i * 256;
                int mm = idx >> 5, kk = idx & 31;
                Bs[kk][mm] = B[(size_t)(n0 + mm) * b_sn + (k0 + kk)];
            }
        } else {
            #pragma unroll
            for (int i = 0; i < 4; i++) {
                int idx = tid + i * 256;
                int mm = idx & 31, kk = idx >> 5;
                Bs[kk][mm] = B[(size_t)(n0 + mm) + (size_t)(k0 + kk) * b_sk];
            }
        }
        __syncthreads();
        #pragma unroll
        for (int kk = 0; kk < 32; kk++) {
            float2 a = *(const float2*)&As[kk][ty * 2];
            float2 b = *(const float2*)&Bs[kk][tx * 2];
            acc[0][0] = fmaf(a.x, b.x, acc[0][0]);
            acc[0][1] = fmaf(a.x, b.y, acc[0][1]);
            acc[1][0] = fmaf(a.y, b.x, acc[1][0]);
            acc[1][1] = fmaf(a.y, b.y, acc[1][1]);
        }
        __syncthreads();
    }
    #pragma unroll
    for (int i = 0; i < 2; i++)
        #pragma unroll
        for (int j = 0; j < 2; j++)
            C[(size_t)(m0 + ty * 2 + i) * c_sm + (n0 + tx * 2 + j)] = acc[i][j];
}

// ---------------- QKV projection, scattered to head-major ----------------
__global__ void __launch_bounds__(256) proj_kernel(
    const float* __restrict__ q_in, const float* __restrict__ k_in,
    const float* __restrict__ v_in, const float* __restrict__ W,
    const float* __restrict__ bias)
{
    int z = blockIdx.z;
    const float* A = (z == 0) ? q_in : (z == 1) ? k_in : v_in;
    float* dst = (z == 0) ? g_q : (z == 1) ? g_k : g_v;
    const float* Bw = W + (size_t)z * 65536;
    const float* bz = bias + z * 256;
    float scale = (z == 0) ? QSCALE : 1.0f;

    int m0 = blockIdx.y * 64, n0 = blockIdx.x * 64;
    __shared__ float As[16][68], Bs[16][68];
    int tid = threadIdx.x;
    int tx = tid & 15, ty = tid >> 4;
    float acc[4][4] = {};
    for (int k0 = 0; k0 < 256; k0 += 16) {
        #pragma unroll
        for (int i = 0; i < 4; i++) {
            int idx = tid + i * 256;
            int mm = idx >> 4, kk = idx & 15;
            As[kk][mm] = A[(size_t)(m0 + mm) * 256 + (k0 + kk)];
            Bs[kk][mm] = Bw[(size_t)(n0 + mm) * 256 + (k0 + kk)];
        }
        __syncthreads();
        #pragma unroll
        for (int kk = 0; kk < 16; kk++) {
            float4 a = *(const float4*)&As[kk][ty * 4];
            float4 b = *(const float4*)&Bs[kk][tx * 4];
            acc[0][0] = fmaf(a.x, b.x, acc[0][0]);
            acc[0][1] = fmaf(a.x, b.y, acc[0][1]);
            acc[0][2] = fmaf(a.x, b.z, acc[0][2]);
            acc[0][3] = fmaf(a.x, b.w, acc[0][3]);
            acc[1][0] = fmaf(a.y, b.x, acc[1][0]);
            acc[1][1] = fmaf(a.y, b.y, acc[1][1]);
            acc[1][2] = fmaf(a.y, b.z, acc[1][2]);
            acc[1][3] = fmaf(a.y, b.w, acc[1][3]);
            acc[2][0] = fmaf(a.z, b.x, acc[2][0]);
            acc[2][1] = fmaf(a.z, b.y, acc[2][1]);
            acc[2][2] = fmaf(a.z, b.z, acc[2][2]);
            acc[2][3] = fmaf(a.z, b.w, acc[2][3]);
            acc[3][0] = fmaf(a.w, b.x, acc[3][0]);
            acc[3][1] = fmaf(a.w, b.y, acc[3][1]);
            acc[3][2] = fmaf(a.w, b.z, acc[3][2]);
            acc[3][3] = fmaf(a.w, b.w, acc[3][3]);
        }
        __syncthreads();
    }
    #pragma unroll
    for (int i = 0; i < 4; i++) {
        int m = m0 + ty * 4 + i;
        int t = m >> 2, b = m & 3;
        #pragma unroll
        for (int j = 0; j < 4; j++) {
            int n = n0 + tx * 4 + j;
            int h = n >> 5, hd = n & 31;
            float val = (acc[i][j] + bz[n]) * scale;
            dst[(size_t)((b * 8 + h) * 768 + t) * 32 + hd] = val;
        }
    }
}

// ---------------- fused flash attention + branch combine, HMMA PV ----------------
// S = QK^T in fp32 SIMT (4x4 tiles); W,V staged as half2; PV via
// mma.m16n8k16.f16 with fp32 accumulate (identical rounding to convert+FFMA).
__global__ void __launch_bounds__(256, 3) flash_kernel()
{
    const int segS[3] = {0, 300, 550};
    const int segE[3] = {300, 550, 768};
    const int bmask[7] = {7, 3, 5, 6, 1, 2, 4};

    int bh = blockIdx.y, t0 = blockIdx.x * 64;
    int tid = threadIdx.x;
    int lane = tid & 31, wid = tid >> 5;
    int tx = tid & 15, ty = tid >> 4;   // S/exp mapping: rows ty*4+i, cols tx*4+j
    int fg = lane >> 2, ft = lane & 3;  // mma fragment coords (group, thread-in-group)
    int warpRow = (wid & 3) * 16;       // PV: warp's 16-row block
    int warpHd = (wid >> 2) * 16;       // PV: warp's 16-hd half

    __shared__ float QsT[32][68], KsT[32][68];
    __shared__ __half2 Wsh[64][36];     // [row][s pair], stride 36 h2 = 144B (conflict-free frags)
    __shared__ __half2 Vsh[32][36];     // [hd][s pair]
    __shared__ float sl_s[3][64];
    __shared__ float srd[7][64];

    const float* qbase = g_q + (size_t)bh * 24576 + (size_t)t0 * 32;
    const float* kb = g_k + (size_t)bh * 24576;
    const float* vb = g_v + (size_t)bh * 24576;

    #pragma unroll
    for (int i = 0; i < 8; i++) {
        int idx = tid + i * 256;
        int r = idx >> 5, kk = idx & 31;
        QsT[kk][r] = qbase[r * 32 + kk];
    }

    // acc[seg][nt][4]: C fragments, warp block 16 rows x (2 n-tiles of 8 hd)
    float acc[3][2][4] = {};

    #pragma unroll
    for (int seg = 0; seg < 3; seg++) {
        int ss = segS[seg], se = segE[seg];
        int ts = ss >> 6, te = (se + 63) >> 6;
        float lpart[4];
        #pragma unroll
        for (int i = 0; i < 4; i++) lpart[i] = 0.0f;

        for (int st = ts; st < te; st++) {
            int s0 = st * 64;
            __syncthreads();
            #pragma unroll
            for (int i = 0; i < 8; i++) {
                int idx = tid + i * 256;
                int r = idx >> 5, kk = idx & 31;
                KsT[kk][r] = kb[(size_t)(s0 + r) * 32 + kk];
            }
            // V tile -> half2, transposed: Vsh[hd][sc2] = (v[2sc2][hd], v[2sc2+1][hd])
            #pragma unroll
            for (int i = 0; i < 4; i++) {
                int idx = tid + i * 256;          // 0..1023
                int sc2 = idx >> 5, hd = idx & 31;
                float v0 = vb[(size_t)(s0 + 2 * sc2) * 32 + hd];
                float v1 = vb[(size_t)(s0 + 2 * sc2 + 1) * 32 + hd];
                Vsh[hd][sc2] = __floats2half2_rn(v0, v1);
            }
            __syncthreads();

            // S tile 4x4: rows ty*4+i, cols tx*4+j (fp32 SIMT)
            float sv[4][4] = {};
            #pragma unroll
            for (int kk = 0; kk < 32; kk++) {
                float4 a = *(const float4*)&QsT[kk][ty * 4];
                float4 b = *(const float4*)&KsT[kk][tx * 4];
                sv[0][0] = fmaf(a.x, b.x, sv[0][0]);
                sv[0][1] = fmaf(a.x, b.y, sv[0][1]);
                sv[0][2] = fmaf(a.x, b.z, sv[0][2]);
                sv[0][3] = fmaf(a.x, b.w, sv[0][3]);
                sv[1][0] = fmaf(a.y, b.x, sv[1][0]);
                sv[1][1] = fmaf(a.y, b.y, sv[1][1]);
                sv[1][2] = fmaf(a.y, b.z, sv[1][2]);
                sv[1][3] = fmaf(a.y, b.w, sv[1][3]);
                sv[2][0] = fmaf(a.z, b.x, sv[2][0]);
                sv[2][1] = fmaf(a.z, b.y, sv[2][1]);
                sv[2][2] = fmaf(a.z, b.z, sv[2][2]);
                sv[2][3] = fmaf(a.z, b.w, sv[2][3]);
                sv[3][0] = fmaf(a.w, b.x, sv[3][0]);
                sv[3][1] = fmaf(a.w, b.y, sv[3][1]);
                sv[3][2] = fmaf(a.w, b.z, sv[3][2]);
                sv[3][3] = fmaf(a.w, b.w, sv[3][3]);
            }

            // exp (bounded), per-row fp32 partial sums (pre-round), half2 W store
            int cb = s0 + tx * 4;
            #pragma unroll
            for (int i = 0; i < 4; i++) {
                float w0 = (cb + 0 >= ss && cb + 0 < se) ? fexp2(sv[i][0]) : 0.0f;
                float w1 = (cb + 1 >= ss && cb + 1 < se) ? fexp2(sv[i][1]) : 0.0f;
                float w2 = (cb + 2 >= ss && cb + 2 < se) ? fexp2(sv[i][2]) : 0.0f;
                float w3 = (cb + 3 >= ss && cb + 3 < se) ? fexp2(sv[i][3]) : 0.0f;
                lpart[i] += (w0 + w1) + (w2 + w3);
                __half2 p0 = __floats2half2_rn(w0, w1);
                __half2 p1 = __floats2half2_rn(w2, w3);
                *(uint2*)&Wsh[ty * 4 + i][tx * 2] =
                    make_uint2(h2_as_u32(p0), h2_as_u32(p1));
            }
            __syncthreads();

            // PV via tensor cores: per warp, 16 rows x 16 hd, K=64 (4 k-steps)
            #pragma unroll
            for (int ks = 0; ks < 4; ks++) {
                int kh = ks * 8;   // half2 col index (16 halves per k-step)
                uint32_t a0 = h2_as_u32(Wsh[warpRow + fg][kh + ft]);
                uint32_t a1 = h2_as_u32(Wsh[warpRow + fg + 8][kh + ft]);
                uint32_t a2 = h2_as_u32(Wsh[warpRow + fg][kh + ft + 4]);
                uint32_t a3 = h2_as_u32(Wsh[warpRow + fg + 8][kh + ft + 4]);
                #pragma unroll
                for (int nt = 0; nt < 2; nt++) {
                    int n0 = warpHd + nt * 8;
                    uint32_t b0 = h2_as_u32(Vsh[n0 + fg][kh + ft]);
                    uint32_t b1 = h2_as_u32(Vsh[n0 + fg][kh + ft + 4]);
                    mma_f16(acc[seg][nt], a0, a1, a2, a3, b0, b1);
                }
            }
        }
        // reduce per-row l across the 16 column-threads (width-16 shuffle)
        #pragma unroll
        for (int i = 0; i < 4; i++) {
            float lf = lpart[i];
            #pragma unroll
            for (int o = 8; o; o >>= 1)
                lf += __shfl_xor_sync(0xffffffffu, lf, o, 16);
            if (tx == 0) sl_s[seg][ty * 4 + i] = lf;
        }
    }
    __syncthreads();

    // per-row reciprocal denominators for all 7 branches (once)
    if (tid < 64) {
        float lr[3] = {sl_s[0][tid], sl_s[1][tid], sl_s[2][tid]};
        #pragma unroll
        for (int br = 0; br < 7; br++) {
            int mask = bmask[br];
            float den = 0.0f;
            #pragma unroll
            for (int s = 0; s < 3; s++)
                if ((mask >> s) & 1) den += lr[s];
            srd[br][tid] = __frcp_rn(den);
        }
    }
    __syncthreads();

    // combine in fragment coordinates: lane owns rows (warpRow+fg, +8),
    // hd cols warpHd + nt*8 + 2*ft, +1. C frag: c0,c1 = row fg; c2,c3 = row fg+8.
    #pragma unroll
    for (int rw = 0; rw < 2; rw++) {
        int r = warpRow + fg + rw * 8;
        int t = t0 + r;
        int seg_t = (t < 300) ? 0 : (t < 550) ? 1 : 2;
        #pragma unroll
        for (int nt = 0; nt < 2; nt++) {
            int hd = warpHd + nt * 8 + ft * 2;
            #pragma unroll
            for (int br = 0; br < 7; br++) {
                int mask = bmask[br];
                float2 val = make_float2(0.0f, 0.0f);
                if ((mask >> seg_t) & 1) {
                    float num0 = 0.0f, num1 = 0.0f;
                    #pragma unroll
                    for (int s = 0; s < 3; s++) {
                        if ((mask >> s) & 1) {
                            num0 += acc[s][nt][rw * 2 + 0];
                            num1 += acc[s][nt][rw * 2 + 1];
                        }
                    }
                    float rd = srd[br][r];
                    val.x = num0 * rd;
                    val.y = num1 * rd;
                }
                *(float2*)&g_obuf[(size_t)br * 786432 + (size_t)bh * 24576 +
                                  (size_t)t * 32 + hd] = val;
            }
        }
    }
}

// ---------------- build G_i = sums of s_*_w column blocks ----------------
__global__ void __launch_bounds__(256) gmat_kernel(
    const float* __restrict__ sl, const float* __restrict__ sa,
    const float* __restrict__ sv)
{
    int idx = blockIdx.x * 256 + threadIdx.x;
    int i = idx >> 16;
    int y = (idx >> 8) & 255;
    int x = idx & 255;
    size_t r = (size_t)y * 1024;
    float v = 0.0f;
    switch (i) {
        case 0: v = sl[r + x]       + sa[r + x]       + sv[r + x];   break;
        case 1: v = sl[r + 256 + x] + sa[r + 256 + x];               break;
        case 2: v = sl[r + 512 + x] + sv[r + 256 + x];               break;
        case 3: v = sa[r + 512 + x] + sv[r + 512 + x];               break;
        case 4: v = sl[r + 768 + x];                                 break;
        case 5: v = sa[r + 768 + x];                                 break;
        case 6: v = sv[r + 768 + x];                                 break;
    }
    g_G[idx] = v;
}

// ---------------- bias fold, stage 1 ----------------
__global__ void __launch_bounds__(256) bias1_kernel(
    const float* __restrict__ out_b, const float* __restrict__ slb,
    const float* __restrict__ sab, const float* __restrict__ svb)
{
    int y = blockIdx.x;
    int tid = threadIdx.x;
    __shared__ float red[256];
    float p = 0.0f;
    #pragma unroll
    for (int i = 0; i < 7; i++)
        p += out_b[i * 256 + tid] * g_G[i * 65536 + y * 256 + tid];
    red[tid] = p;
    __syncthreads();
    for (int o = 128; o; o >>= 1) {
        if (tid < o) red[tid] += red[tid + o];
        __syncthreads();
    }
    if (tid == 0) g_c1[y] = red[0] + slb[y] + sab[y] + svb[y];
}

// ---------------- bias fold, stage 2 ----------------
__global__ void __launch_bounds__(256) bias2_kernel(
    const float* __restrict__ fb, const float* __restrict__ fw)
{
    int n = blockIdx.x;
    int tid = threadIdx.x;
    __shared__ float red[256];
    red[tid] = g_c1[tid] * fw[(size_t)n * 256 + tid];
    __syncthreads();
    for (int o = 128; o; o >>= 1) {
        if (tid < o) red[tid] += red[tid + o];
        __syncthreads();
    }
    if (tid == 0) g_biasv[n] = red[0] + fb[n];
}

// ---------------- final fused GEMM: out = sum_i o_i @ M_i + bias (dead-branch skip) ----------------
__global__ void __launch_bounds__(256) final_kernel(float* __restrict__ out)
{
    int m0 = blockIdx.y * 64, n0 = blockIdx.x * 32;
    __shared__ float As[32][68], Bs[32][36];
    int tid = threadIdx.x;
    int tx = tid & 15, ty = tid >> 4;

    int tb0 = m0 >> 2, tb1 = (m0 + 63) >> 2;
    int bm = 0;
    #pragma unroll
    for (int br = 0; br < 7; br++) {
        int mk = c_bmask[br];
        #pragma unroll
        for (int s = 0; s < 3; s++)
            if (((mk >> s) & 1) && tb0 < c_segE[s] && tb1 >= c_segS[s]) bm |= 1 << br;
    }

    float acc[4][2] = {};
    for (int k0 = 0; k0 < 1792; k0 += 32) {
        int ibr = k0 >> 8;
        if (!((bm >> ibr) & 1)) continue;
        int h = (k0 & 255) >> 5;
        const float* Abase = g_obuf + (size_t)ibr * 786432 + (size_t)h * 24576;
        #pragma unroll
        for (int i = 0; i < 8; i++) {
            int idx = tid + i * 256;
            int mm = idx >> 5, kk = idx & 31;
            int m = m0 + mm;
            int t = m >> 2, b = m & 3;
            As[kk][mm] = Abase[(size_t)b * 196608 + (size_t)t * 32 + kk];
        }
        #pragma unroll
        for (int i = 0; i < 4; i++) {
            int idx = tid + i * 256;
            int nn = idx >> 5, kk = idx & 31;
            Bs[kk][nn] = g_MTcat[(size_t)(n0 + nn) * 1792 + k0 + kk];
        }
        __syncthreads();
        #pragma unroll
        for (int kk = 0; kk < 32; kk++) {
            float4 a = *(const float4*)&As[kk][ty * 4];
            float2 b = *(const float2*)&Bs[kk][tx * 2];
            acc[0][0] = fmaf(a.x, b.x, acc[0][0]);
            acc[0][1] = fmaf(a.x, b.y, acc[0][1]);
            acc[1][0] = fmaf(a.y, b.x, acc[1][0]);
            acc[1][1] = fmaf(a.y, b.y, acc[1][1]);
            acc[2][0] = fmaf(a.z, b.x, acc[2][0]);
            acc[2][1] = fmaf(a.z, b.y, acc[2][1]);
            acc[3][0] = fmaf(a.w, b.x, acc[3][0]);
            acc[3][1] = fmaf(a.w, b.y, acc[3][1]);
        }
        __syncthreads();
    }
    #pragma unroll
    for (int i = 0; i < 4; i++) {
        int m = m0 + ty * 4 + i;
        #pragma unroll
        for (int j = 0; j < 2; j++) {
            int n = n0 + tx * 2 + j;
            out[(size_t)m * 256 + n] = acc[i][j] + g_biasv[n];
        }
    }
}

// ---------------- launch (serial; flash kept as 4th launch for ncu) ----------------
extern "C" void kernel_launch(void* const* d_in, const int* in_sizes, int n_in,
                              void* d_out, int out_size)
{
    const float* query     = (const float*)d_in[0];
    const float* key       = (const float*)d_in[1];
    const float* value     = (const float*)d_in[2];
    const float* in_proj_w = (const float*)d_in[3];
    const float* in_proj_b = (const float*)d_in[4];
    const float* out_w     = (const float*)d_in[5];
    const float* out_b     = (const float*)d_in[6];
    const float* s_l_w     = (const float*)d_in[7];
    const float* s_l_b     = (const float*)d_in[8];
    const float* s_a_w     = (const float*)d_in[9];
    const float* s_a_b     = (const float*)d_in[10];
    const float* s_v_w     = (const float*)d_in[11];
    const float* s_v_b     = (const float*)d_in[12];
    const float* final_w   = (const float*)d_in[13];
    const float* final_b   = (const float*)d_in[14];
    float* out = (float*)d_out;
    (void)in_sizes; (void)n_in; (void)out_size;

    float *p_G, *p_tmpT, *p_MTcat;
    cudaGetSymbolAddress((void**)&p_G,      g_G);
    cudaGetSymbolAddress((void**)&p_tmpT,   g_tmpT);
    cudaGetSymbolAddress((void**)&p_MTcat,  g_MTcat);

    // launch #1: q/k/v projections -> head-major
    proj_kernel<<<dim3(4, 48, 3), 256>>>(query, key, value, in_proj_w, in_proj_b);

    // launch #2: G_i (weights only)
    gmat_kernel<<<1792, 256>>>(s_l_w, s_a_w, s_v_w);

    // launch #3: tmpT[i][a][y] = sum_x out_w[i][x][a] * G_i[y][x]
    gemm_small<<<dim3(8, 8, 7), 256>>>(
        out_w, 1, 256, 65536,
        p_G, 256, 1, 65536,
        p_tmpT, 256, 65536, 256);

    // launch #4: fused flash attention + branch combine  (ncu profiles this one)
    flash_kernel<<<dim3(12, 32), 256>>>();

    // launch #5: MTcat[n][i*256+a] = sum_y final_w[n][y] * tmpT[i][a][y]
    gemm_small<<<dim3(8, 8, 7), 256>>>(
        final_w, 256, 1, 0,
        p_tmpT, 256, 1, 65536,
        p_MTcat, 1792, 256, 256);

    // launches #6,#7: fold biases
    bias1_kernel<<<256, 256>>>(out_b, s_l_b, s_a_b, s_v_b);
    bias2_kernel<<<256, 256>>>(final_b, final_w);

    // launch #8: out = sum_i o_i @ M_i + bias
    final_kernel<<<dim3(8, 48), 256>>>(out);
}

// round 17
// speedup vs baseline: 1.5501x; 1.0973x over previous
#include <cuda_runtime.h>
#include <cuda_fp16.h>
#include <math.h>
#include <stdint.h>

// Problem constants: T=768, B=4, E=256, H=8, HD=32, 32 "bh" heads.
// Q scale folded with log2(e): scores arrive in log2 domain, exp(s) == 2^s'.
#define QSCALE 0.25500917392938054f   // (1/sqrt(32)) * log2(e)

// ---------------- scratch (static device globals; no allocation) ----------------
__device__ float g_q[786432];        // [bh=32][t=768][hd=32]
__device__ float g_k[786432];
__device__ float g_v[786432];
__device__ float g_obuf[5505024];    // [branch=7][bh=32][t=768][hd=32]
__device__ float g_G[458752];        // [7][y=256][x=256]
__device__ float g_tmpT[458752];     // [7][a=256][y=256]
__device__ float g_MTcat[458752];    // [n=256][k=1792]
__device__ float g_c1[256];
__device__ float g_biasv[256];

// Segments partition the columns: L=[0,300) A=[300,550) V=[550,768)
__constant__ int c_segS[3] = {0, 300, 550};
__constant__ int c_segE[3] = {300, 550, 768};
// branch -> segment bitmask: lav, la, lv, av, l, a, v
__constant__ int c_bmask[7] = {7, 3, 5, 6, 1, 2, 4};

// bit-cast helpers (no SASS cost)
__device__ __forceinline__ uint32_t h2_as_u32(__half2 h) {
    return *reinterpret_cast<uint32_t*>(&h);
}

// FMA-pipe 2^x (no MUFU). |x| < ~80, rel err ~1e-7 (deg-6 Taylor on [-0.5,0.5]).
__device__ __forceinline__ float fexp2(float x)
{
    float z = x + 12582912.0f;            // 1.5*2^23: round-to-nearest-int trick
    int   n = __float_as_int(z);          // low bits hold round(x)
    float f = x - (z - 12582912.0f);      // frac in [-0.5, 0.5], exact
    float p = 1.5402387e-4f;
    p = fmaf(p, f, 1.3333558e-3f);
    p = fmaf(p, f, 9.6181291e-3f);
    p = fmaf(p, f, 5.5504109e-2f);
    p = fmaf(p, f, 2.4022651e-1f);
    p = fmaf(p, f, 6.9314718e-1f);
    p = fmaf(p, f, 1.0f);
    return __int_as_float(__float_as_int(p) + (n << 23));
}

// m16n8k16 f16 mma with fp32 accumulate (half x half products are exact in fp32)
__device__ __forceinline__ void mma_f16(float* c,
    uint32_t a0, uint32_t a1, uint32_t a2, uint32_t a3,
    uint32_t b0, uint32_t b1)
{
    asm volatile(
        "mma.sync.aligned.m16n8k16.row.col.f32.f16.f16.f32 "
        "{%0,%1,%2,%3}, {%4,%5,%6,%7}, {%8,%9}, {%0,%1,%2,%3};"
        : "+f"(c[0]), "+f"(c[1]), "+f"(c[2]), "+f"(c[3])
        : "r"(a0), "r"(a1), "r"(a2), "r"(a3), "r"(b0), "r"(b1));
}

// ---------------- small tiled SGEMM (32x32 tiles, K-step 32), coalesced ----------------
__global__ void __launch_bounds__(256) gemm_small(
    const float* __restrict__ A, int a_sm, int a_sk, int a_bz,
    const float* __restrict__ B, int b_sn, int b_sk, int b_bz,
    float* __restrict__ C, int c_sm, int c_bz,
    int K)
{
    A += (size_t)blockIdx.z * a_bz;
    B += (size_t)blockIdx.z * b_bz;
    C += (size_t)blockIdx.z * c_bz;
    int m0 = blockIdx.y * 32, n0 = blockIdx.x * 32;
    __shared__ float As[32][36], Bs[32][36];
    int tid = threadIdx.x;
    int tx = tid & 15, ty = tid >> 4;
    float acc[2][2] = {};
    for (int k0 = 0; k0 < K; k0 += 32) {
        if (a_sk == 1) {
            #pragma unroll
            for (int i = 0; i < 4; i++) {
                int idx = tid + i * 256;
                int mm = idx >> 5, kk = idx & 31;
                As[kk][mm] = A[(size_t)(m0 + mm) * a_sm + (k0 + kk)];
            }
        } else {
            #pragma unroll
            for (int i = 0; i < 4; i++) {
                int idx = tid + i * 256;
                int mm = idx & 31, kk = idx >> 5;
                As[kk][mm] = A[(size_t)(m0 + mm) + (size_t)(k0 + kk) * a_sk];
            }
        }
        if (b_sk == 1) {
            #pragma unroll
            for (int i = 0; i < 4; i++) {
                int idx = tid + i * 256;
                int mm = idx >> 5, kk = idx & 31;
                Bs[kk][mm] = B[(size_t)(n0 + mm) * b_sn + (k0 + kk)];
            }
        } else {
            #pragma unroll
            for (int i = 0; i < 4; i++) {
                int idx = tid + i * 256;
                int mm = idx & 31, kk = idx >> 5;
                Bs[kk][mm] = B[(size_t)(n0 + mm) + (size_t)(k0 + kk) * b_sk];
            }
        }
        __syncthreads();
        #pragma unroll
        for (int kk = 0; kk < 32; kk++) {
            float2 a = *(const float2*)&As[kk][ty * 2];
            float2 b = *(const float2*)&Bs[kk][tx * 2];
            acc[0][0] = fmaf(a.x, b.x, acc[0][0]);
            acc[0][1] = fmaf(a.x, b.y, acc[0][1]);
            acc[1][0] = fmaf(a.y, b.x, acc[1][0]);
            acc[1][1] = fmaf(a.y, b.y, acc[1][1]);
        }
        __syncthreads();
    }
    #pragma unroll
    for (int i = 0; i < 2; i++)
        #pragma unroll
        for (int j = 0; j < 2; j++)
            C[(size_t)(m0 + ty * 2 + i) * c_sm + (n0 + tx * 2 + j)] = acc[i][j];
}

// ---------------- QKV projection, scattered to head-major ----------------
__global__ void __launch_bounds__(256) proj_kernel(
    const float* __restrict__ q_in, const float* __restrict__ k_in,
    const float* __restrict__ v_in, const float* __restrict__ W,
    const float* __restrict__ bias)
{
    int z = blockIdx.z;
    const float* A = (z == 0) ? q_in : (z == 1) ? k_in : v_in;
    float* dst = (z == 0) ? g_q : (z == 1) ? g_k : g_v;
    const float* Bw = W + (size_t)z * 65536;
    const float* bz = bias + z * 256;
    float scale = (z == 0) ? QSCALE : 1.0f;

    int m0 = blockIdx.y * 64, n0 = blockIdx.x * 64;
    __shared__ float As[16][68], Bs[16][68];
    int tid = threadIdx.x;
    int tx = tid & 15, ty = tid >> 4;
    float acc[4][4] = {};
    for (int k0 = 0; k0 < 256; k0 += 16) {
        #pragma unroll
        for (int i = 0; i < 4; i++) {
            int idx = tid + i * 256;
            int mm = idx >> 4, kk = idx & 15;
            As[kk][mm] = A[(size_t)(m0 + mm) * 256 + (k0 + kk)];
            Bs[kk][mm] = Bw[(size_t)(n0 + mm) * 256 + (k0 + kk)];
        }
        __syncthreads();
        #pragma unroll
        for (int kk = 0; kk < 16; kk++) {
            float4 a = *(const float4*)&As[kk][ty * 4];
            float4 b = *(const float4*)&Bs[kk][tx * 4];
            acc[0][0] = fmaf(a.x, b.x, acc[0][0]);
            acc[0][1] = fmaf(a.x, b.y, acc[0][1]);
            acc[0][2] = fmaf(a.x, b.z, acc[0][2]);
            acc[0][3] = fmaf(a.x, b.w, acc[0][3]);
            acc[1][0] = fmaf(a.y, b.x, acc[1][0]);
            acc[1][1] = fmaf(a.y, b.y, acc[1][1]);
            acc[1][2] = fmaf(a.y, b.z, acc[1][2]);
            acc[1][3] = fmaf(a.y, b.w, acc[1][3]);
            acc[2][0] = fmaf(a.z, b.x, acc[2][0]);
            acc[2][1] = fmaf(a.z, b.y, acc[2][1]);
            acc[2][2] = fmaf(a.z, b.z, acc[2][2]);
            acc[2][3] = fmaf(a.z, b.w, acc[2][3]);
            acc[3][0] = fmaf(a.w, b.x, acc[3][0]);
            acc[3][1] = fmaf(a.w, b.y, acc[3][1]);
            acc[3][2] = fmaf(a.w, b.z, acc[3][2]);
            acc[3][3] = fmaf(a.w, b.w, acc[3][3]);
        }
        __syncthreads();
    }
    #pragma unroll
    for (int i = 0; i < 4; i++) {
        int m = m0 + ty * 4 + i;
        int t = m >> 2, b = m & 3;
        #pragma unroll
        for (int j = 0; j < 4; j++) {
            int n = n0 + tx * 4 + j;
            int h = n >> 5, hd = n & 31;
            float val = (acc[i][j] + bz[n]) * scale;
            dst[(size_t)((b * 8 + h) * 768 + t) * 32 + hd] = val;
        }
    }
}

// ---------------- fused flash attention + branch combine, full HMMA ----------------
// S = QK^T via 3-pass split-f16 HMMA (Qh*Kh + Qh*Kl + Ql*Kh, err ~2^-22);
// exp in fragment coords; PV via f16 HMMA with fp32 accumulate (as R16).
__global__ void __launch_bounds__(256, 3) flash_kernel()
{
    const int segS[3] = {0, 300, 550};
    const int segE[3] = {300, 550, 768};
    const int bmask[7] = {7, 3, 5, 6, 1, 2, 4};

    int bh = blockIdx.y, t0 = blockIdx.x * 64;
    int tid = threadIdx.x;
    int lane = tid & 31, wid = tid >> 5;
    int fg = lane >> 2, ft = lane & 3;  // fragment coords (group, thread-in-group)
    int warpRow = (wid & 3) * 16;       // warp's 16-row block
    int wch = wid >> 2;                 // column half (0/1)
    int warpCol = wch * 32;             // S: warp's 32 s-columns
    int warpHd = wch * 16;              // PV: warp's 16-hd half

    __shared__ __half2 Qh[64][18], Ql[64][18];   // [t-row][hd pair] (+2 pad)
    __shared__ __half2 Kh[64][18], Kl[64][18];   // [s-row][hd pair]
    __shared__ __half2 Wsh[64][36];              // [t-row][s pair]
    __shared__ __half2 Vsh[32][36];              // [hd][s pair]
    __shared__ float sl_s[3][64];
    __shared__ float srd[7][64];
    __shared__ float sl_tmp[2][64];

    const float* qbase = g_q + (size_t)bh * 24576 + (size_t)t0 * 32;
    const float* kb = g_k + (size_t)bh * 24576;
    const float* vb = g_v + (size_t)bh * 24576;

    // stage Q once, split hi/lo (natural layout, no transpose)
    #pragma unroll
    for (int i = 0; i < 4; i++) {
        int idx = tid + i * 256;        // 0..1023 float2s
        int r = idx >> 4, c2 = idx & 15;
        float2 qv = *(const float2*)&qbase[(size_t)r * 32 + c2 * 2];
        __half2 h = __floats2half2_rn(qv.x, qv.y);
        float2 hb = __half22float2(h);
        Qh[r][c2] = h;
        Ql[r][c2] = __floats2half2_rn(qv.x - hb.x, qv.y - hb.y);
    }

    // PV C fragments: acc[seg][nt][4], warp block 16 rows x (2 n-tiles of 8 hd)
    float acc[3][2][4] = {};

    #pragma unroll
    for (int seg = 0; seg < 3; seg++) {
        int ss = segS[seg], se = segE[seg];
        int ts = ss >> 6, te = (se + 63) >> 6;
        float lp0 = 0.0f, lp1 = 0.0f;   // row sums: rows warpRow+fg, +8 (this warp's cols)

        for (int st = ts; st < te; st++) {
            int s0 = st * 64;
            __syncthreads();
            // stage K tile, split hi/lo
            #pragma unroll
            for (int i = 0; i < 4; i++) {
                int idx = tid + i * 256;
                int r = idx >> 4, c2 = idx & 15;
                float2 kv = *(const float2*)&kb[(size_t)(s0 + r) * 32 + c2 * 2];
                __half2 h = __floats2half2_rn(kv.x, kv.y);
                float2 hb2 = __half22float2(h);
                Kh[r][c2] = h;
                Kl[r][c2] = __floats2half2_rn(kv.x - hb2.x, kv.y - hb2.y);
            }
            // stage V tile (transposed, half2)
            #pragma unroll
            for (int i = 0; i < 4; i++) {
                int idx = tid + i * 256;
                int sc2 = idx >> 5, hd = idx & 31;
                float v0 = vb[(size_t)(s0 + 2 * sc2) * 32 + hd];
                float v1 = vb[(size_t)(s0 + 2 * sc2 + 1) * 32 + hd];
                Vsh[hd][sc2] = __floats2half2_rn(v0, v1);
            }
            __syncthreads();

            // --- S via tensor cores: warp computes 16x32, K=32 (2 k-steps), 3 passes ---
            float sacc[4][4] = {};
            #pragma unroll
            for (int ks = 0; ks < 2; ks++) {
                int kh = ks * 8;
                uint32_t ah0 = h2_as_u32(Qh[warpRow + fg][kh + ft]);
                uint32_t ah1 = h2_as_u32(Qh[warpRow + fg + 8][kh + ft]);
                uint32_t ah2 = h2_as_u32(Qh[warpRow + fg][kh + ft + 4]);
                uint32_t ah3 = h2_as_u32(Qh[warpRow + fg + 8][kh + ft + 4]);
                uint32_t al0 = h2_as_u32(Ql[warpRow + fg][kh + ft]);
                uint32_t al1 = h2_as_u32(Ql[warpRow + fg + 8][kh + ft]);
                uint32_t al2 = h2_as_u32(Ql[warpRow + fg][kh + ft + 4]);
                uint32_t al3 = h2_as_u32(Ql[warpRow + fg + 8][kh + ft + 4]);
                #pragma unroll
                for (int nt = 0; nt < 4; nt++) {
                    int n0 = warpCol + nt * 8;
                    uint32_t bh0 = h2_as_u32(Kh[n0 + fg][kh + ft]);
                    uint32_t bh1 = h2_as_u32(Kh[n0 + fg][kh + ft + 4]);
                    uint32_t bl0 = h2_as_u32(Kl[n0 + fg][kh + ft]);
                    uint32_t bl1 = h2_as_u32(Kl[n0 + fg][kh + ft + 4]);
                    mma_f16(sacc[nt], ah0, ah1, ah2, ah3, bh0, bh1);
                    mma_f16(sacc[nt], ah0, ah1, ah2, ah3, bl0, bl1);
                    mma_f16(sacc[nt], al0, al1, al2, al3, bh0, bh1);
                }
            }

            // exp + mask + row sums + half2 W store (fragment coords)
            #pragma unroll
            for (int nt = 0; nt < 4; nt++) {
                int col0 = s0 + warpCol + nt * 8 + ft * 2;
                bool v0 = (col0 >= ss) && (col0 < se);
                bool v1 = (col0 + 1 >= ss) && (col0 + 1 < se);
                float w0 = v0 ? fexp2(sacc[nt][0]) : 0.0f;
                float w1 = v1 ? fexp2(sacc[nt][1]) : 0.0f;
                float w2 = v0 ? fexp2(sacc[nt][2]) : 0.0f;
                float w3 = v1 ? fexp2(sacc[nt][3]) : 0.0f;
                lp0 += w0 + w1;
                lp1 += w2 + w3;
                int wc = (warpCol >> 1) + nt * 4 + ft;
                Wsh[warpRow + fg][wc]     = __floats2half2_rn(w0, w1);
                Wsh[warpRow + fg + 8][wc] = __floats2half2_rn(w2, w3);
            }
            __syncthreads();

            // --- PV via tensor cores: per warp, 16 rows x 16 hd, K=64 (4 k-steps) ---
            #pragma unroll
            for (int ks = 0; ks < 4; ks++) {
                int kh = ks * 8;
                uint32_t a0 = h2_as_u32(Wsh[warpRow + fg][kh + ft]);
                uint32_t a1 = h2_as_u32(Wsh[warpRow + fg + 8][kh + ft]);
                uint32_t a2 = h2_as_u32(Wsh[warpRow + fg][kh + ft + 4]);
                uint32_t a3 = h2_as_u32(Wsh[warpRow + fg + 8][kh + ft + 4]);
                #pragma unroll
                for (int nt = 0; nt < 2; nt++) {
                    int n0 = warpHd + nt * 8;
                    uint32_t b0 = h2_as_u32(Vsh[n0 + fg][kh + ft]);
                    uint32_t b1 = h2_as_u32(Vsh[n0 + fg][kh + ft + 4]);
                    mma_f16(acc[seg][nt], a0, a1, a2, a3, b0, b1);
                }
            }
        }

        // reduce row sums over ft quad, then across the two column-half warps
        lp0 += __shfl_down_sync(0xffffffffu, lp0, 2, 4);
        lp0 += __shfl_down_sync(0xffffffffu, lp0, 1, 4);
        lp1 += __shfl_down_sync(0xffffffffu, lp1, 2, 4);
        lp1 += __shfl_down_sync(0xffffffffu, lp1, 1, 4);
        if (ft == 0) {
            sl_tmp[wch][warpRow + fg]     = lp0;
            sl_tmp[wch][warpRow + fg + 8] = lp1;
        }
        __syncthreads();
        if (tid < 64) sl_s[seg][tid] = sl_tmp[0][tid] + sl_tmp[1][tid];
        __syncthreads();
    }

    // per-row reciprocal denominators for all 7 branches (once)
    if (tid < 64) {
        float lr[3] = {sl_s[0][tid], sl_s[1][tid], sl_s[2][tid]};
        #pragma unroll
        for (int br = 0; br < 7; br++) {
            int mask = bmask[br];
            float den = 0.0f;
            #pragma unroll
            for (int s = 0; s < 3; s++)
                if ((mask >> s) & 1) den += lr[s];
            srd[br][tid] = __frcp_rn(den);
        }
    }
    __syncthreads();

    // combine in fragment coordinates: lane owns rows (warpRow+fg, +8),
    // hd cols warpHd + nt*8 + 2*ft, +1.
    #pragma unroll
    for (int rw = 0; rw < 2; rw++) {
        int r = warpRow + fg + rw * 8;
        int t = t0 + r;
        int seg_t = (t < 300) ? 0 : (t < 550) ? 1 : 2;
        #pragma unroll
        for (int nt = 0; nt < 2; nt++) {
            int hd = warpHd + nt * 8 + ft * 2;
            #pragma unroll
            for (int br = 0; br < 7; br++) {
                int mask = bmask[br];
                float2 val = make_float2(0.0f, 0.0f);
                if ((mask >> seg_t) & 1) {
                    float num0 = 0.0f, num1 = 0.0f;
                    #pragma unroll
                    for (int s = 0; s < 3; s++) {
                        if ((mask >> s) & 1) {
                            num0 += acc[s][nt][rw * 2 + 0];
                            num1 += acc[s][nt][rw * 2 + 1];
                        }
                    }
                    float rd = srd[br][r];
                    val.x = num0 * rd;
                    val.y = num1 * rd;
                }
                *(float2*)&g_obuf[(size_t)br * 786432 + (size_t)bh * 24576 +
                                  (size_t)t * 32 + hd] = val;
            }
        }
    }
}

// ---------------- build G_i = sums of s_*_w column blocks ----------------
__global__ void __launch_bounds__(256) gmat_kernel(
    const float* __restrict__ sl, const float* __restrict__ sa,
    const float* __restrict__ sv)
{
    int idx = blockIdx.x * 256 + threadIdx.x;
    int i = idx >> 16;
    int y = (idx >> 8) & 255;
    int x = idx & 255;
    size_t r = (size_t)y * 1024;
    float v = 0.0f;
    switch (i) {
        case 0: v = sl[r + x]       + sa[r + x]       + sv[r + x];   break;
        case 1: v = sl[r + 256 + x] + sa[r + 256 + x];               break;
        case 2: v = sl[r + 512 + x] + sv[r + 256 + x];               break;
        case 3: v = sa[r + 512 + x] + sv[r + 512 + x];               break;
        case 4: v = sl[r + 768 + x];                                 break;
        case 5: v = sa[r + 768 + x];                                 break;
        case 6: v = sv[r + 768 + x];                                 break;
    }
    g_G[idx] = v;
}

// ---------------- bias fold, stage 1 ----------------
__global__ void __launch_bounds__(256) bias1_kernel(
    const float* __restrict__ out_b, const float* __restrict__ slb,
    const float* __restrict__ sab, const float* __restrict__ svb)
{
    int y = blockIdx.x;
    int tid = threadIdx.x;
    __shared__ float red[256];
    float p = 0.0f;
    #pragma unroll
    for (int i = 0; i < 7; i++)
        p += out_b[i * 256 + tid] * g_G[i * 65536 + y * 256 + tid];
    red[tid] = p;
    __syncthreads();
    for (int o = 128; o; o >>= 1) {
        if (tid < o) red[tid] += red[tid + o];
        __syncthreads();
    }
    if (tid == 0) g_c1[y] = red[0] + slb[y] + sab[y] + svb[y];
}

// ---------------- bias fold, stage 2 ----------------
__global__ void __launch_bounds__(256) bias2_kernel(
    const float* __restrict__ fb, const float* __restrict__ fw)
{
    int n = blockIdx.x;
    int tid = threadIdx.x;
    __shared__ float red[256];
    red[tid] = g_c1[tid] * fw[(size_t)n * 256 + tid];
    __syncthreads();
    for (int o = 128; o; o >>= 1) {
        if (tid < o) red[tid] += red[tid + o];
        __syncthreads();
    }
    if (tid == 0) g_biasv[n] = red[0] + fb[n];
}

// ---------------- final fused GEMM: out = sum_i o_i @ M_i + bias (dead-branch skip) ----------------
__global__ void __launch_bounds__(256) final_kernel(float* __restrict__ out)
{
    int m0 = blockIdx.y * 64, n0 = blockIdx.x * 32;
    __shared__ float As[32][68], Bs[32][36];
    int tid = threadIdx.x;
    int tx = tid & 15, ty = tid >> 4;

    int tb0 = m0 >> 2, tb1 = (m0 + 63) >> 2;
    int bm = 0;
    #pragma unroll
    for (int br = 0; br < 7; br++) {
        int mk = c_bmask[br];
        #pragma unroll
        for (int s = 0; s < 3; s++)
            if (((mk >> s) & 1) && tb0 < c_segE[s] && tb1 >= c_segS[s]) bm |= 1 << br;
    }

    float acc[4][2] = {};
    for (int k0 = 0; k0 < 1792; k0 += 32) {
        int ibr = k0 >> 8;
        if (!((bm >> ibr) & 1)) continue;
        int h = (k0 & 255) >> 5;
        const float* Abase = g_obuf + (size_t)ibr * 786432 + (size_t)h * 24576;
        #pragma unroll
        for (int i = 0; i < 8; i++) {
            int idx = tid + i * 256;
            int mm = idx >> 5, kk = idx & 31;
            int m = m0 + mm;
            int t = m >> 2, b = m & 3;
            As[kk][mm] = Abase[(size_t)b * 196608 + (size_t)t * 32 + kk];
        }
        #pragma unroll
        for (int i = 0; i < 4; i++) {
            int idx = tid + i * 256;
            int nn = idx >> 5, kk = idx & 31;
            Bs[kk][nn] = g_MTcat[(size_t)(n0 + nn) * 1792 + k0 + kk];
        }
        __syncthreads();
        #pragma unroll
        for (int kk = 0; kk < 32; kk++) {
            float4 a = *(const float4*)&As[kk][ty * 4];
            float2 b = *(const float2*)&Bs[kk][tx * 2];
            acc[0][0] = fmaf(a.x, b.x, acc[0][0]);
            acc[0][1] = fmaf(a.x, b.y, acc[0][1]);
            acc[1][0] = fmaf(a.y, b.x, acc[1][0]);
            acc[1][1] = fmaf(a.y, b.y, acc[1][1]);
            acc[2][0] = fmaf(a.z, b.x, acc[2][0]);
            acc[2][1] = fmaf(a.z, b.y, acc[2][1]);
            acc[3][0] = fmaf(a.w, b.x, acc[3][0]);
            acc[3][1] = fmaf(a.w, b.y, acc[3][1]);
        }
        __syncthreads();
    }
    #pragma unroll
    for (int i = 0; i < 4; i++) {
        int m = m0 + ty * 4 + i;
        #pragma unroll
        for (int j = 0; j < 2; j++) {
            int n = n0 + tx * 2 + j;
            out[(size_t)m * 256 + n] = acc[i][j] + g_biasv[n];
        }
    }
}

// ---------------- launch (serial; flash kept as 4th launch for ncu) ----------------
extern "C" void kernel_launch(void* const* d_in, const int* in_sizes, int n_in,
                              void* d_out, int out_size)
{
    const float* query     = (const float*)d_in[0];
    const float* key       = (const float*)d_in[1];
    const float* value     = (const float*)d_in[2];
    const float* in_proj_w = (const float*)d_in[3];
    const float* in_proj_b = (const float*)d_in[4];
    const float* out_w     = (const float*)d_in[5];
    const float* out_b     = (const float*)d_in[6];
    const float* s_l_w     = (const float*)d_in[7];
    const float* s_l_b     = (const float*)d_in[8];
    const float* s_a_w     = (const float*)d_in[9];
    const float* s_a_b     = (const float*)d_in[10];
    const float* s_v_w     = (const float*)d_in[11];
    const float* s_v_b     = (const float*)d_in[12];
    const float* final_w   = (const float*)d_in[13];
    const float* final_b   = (const float*)d_in[14];
    float* out = (float*)d_out;
    (void)in_sizes; (void)n_in; (void)out_size;

    float *p_G, *p_tmpT, *p_MTcat;
    cudaGetSymbolAddress((void**)&p_G,      g_G);
    cudaGetSymbolAddress((void**)&p_tmpT,   g_tmpT);
    cudaGetSymbolAddress((void**)&p_MTcat,  g_MTcat);

    // launch #1: q/k/v projections -> head-major
    proj_kernel<<<dim3(4, 48, 3), 256>>>(query, key, value, in_proj_w, in_proj_b);

    // launch #2: G_i (weights only)
    gmat_kernel<<<1792, 256>>>(s_l_w, s_a_w, s_v_w);

    // launch #3: tmpT[i][a][y] = sum_x out_w[i][x][a] * G_i[y][x]
    gemm_small<<<dim3(8, 8, 7), 256>>>(
        out_w, 1, 256, 65536,
        p_G, 256, 1, 65536,
        p_tmpT, 256, 65536, 256);

    // launch #4: fused flash attention + branch combine  (ncu profiles this one)
    flash_kernel<<<dim3(12, 32), 256>>>();

    // launch #5: MTcat[n][i*256+a] = sum_y final_w[n][y] * tmpT[i][a][y]
    gemm_small<<<dim3(8, 8, 7), 256>>>(
        final_w, 256, 1, 0,
        p_tmpT, 256, 1, 65536,
        p_MTcat, 1792, 256, 256);

    // launches #6,#7: fold biases
    bias1_kernel<<<256, 256>>>(out_b, s_l_b, s_a_b, s_v_b);
    bias2_kernel<<<256, 256>>>(final_b, final_w);

    // launch #8: out = sum_i o_i @ M_i + bias
    final_kernel<<<dim3(8, 48), 256>>>(out);
}